// round 2
// baseline (speedup 1.0000x reference)
#include <cuda_runtime.h>
#include <cstdint>

#define B_TOK 8192
#define C_DIM 1024
#define E_NUM 8
#define K_TOP 4
#define H_DIM 4096

// ---------------- scratch (device globals; no allocations allowed) ----------------
__device__ int   g_count[E_NUM];
__device__ int   g_tok[E_NUM * B_TOK];            // expert bucket -> token id
__device__ int   g_te[B_TOK * K_TOP];             // token -> chosen expert
__device__ int   g_tp[B_TOK * K_TOP];             // token -> position in expert bucket
__device__ float g_tw[B_TOK * K_TOP];             // token -> gate weight (softmax prob)
__device__ float g_h[(size_t)E_NUM * B_TOK * H_DIM];   // hidden activations (1 GiB)
__device__ float g_y[(size_t)E_NUM * B_TOK * C_DIM];   // expert outputs pre-LN (256 MiB)

// ---------------- helpers ----------------
__device__ __forceinline__ uint32_t f2tf32(float f) {
    uint32_t u;
    asm("cvt.rna.tf32.f32 %0, %1;" : "=r"(u) : "f"(f));
    return u;
}

__device__ __forceinline__ void mma_tf32(float (&d)[4], const uint32_t (&a)[4], const uint32_t (&b)[2]) {
    asm volatile(
        "mma.sync.aligned.m16n8k8.row.col.f32.tf32.tf32.f32 "
        "{%0,%1,%2,%3}, {%4,%5,%6,%7}, {%8,%9}, {%0,%1,%2,%3};\n"
        : "+f"(d[0]), "+f"(d[1]), "+f"(d[2]), "+f"(d[3])
        : "r"(a[0]), "r"(a[1]), "r"(a[2]), "r"(a[3]), "r"(b[0]), "r"(b[1]));
}

__device__ __forceinline__ float quick_gelu(float v) {
    return v / (1.f + __expf(-1.702f * v));
}

// ---------------- kernel 0: reset counters ----------------
__global__ void zero_counts() {
    if (threadIdx.x < E_NUM) g_count[threadIdx.x] = 0;
}

// ---------------- kernel 1: gating (fp32), softmax, top-4, bucket ----------------
__global__ void gate_kernel(const float* __restrict__ x,
                            const float* __restrict__ Wg,
                            const float* __restrict__ bg) {
    const int warp = threadIdx.x >> 5;
    const int lane = threadIdx.x & 31;
    const int b = blockIdx.x * 8 + warp;

    float acc[E_NUM];
#pragma unroll
    for (int e = 0; e < E_NUM; e++) acc[e] = 0.f;

    const float* xr = x + (size_t)b * C_DIM;
    for (int c = lane; c < C_DIM; c += 32) {
        float xv = xr[c];
        const float* wr = Wg + c * E_NUM;
#pragma unroll
        for (int e = 0; e < E_NUM; e++) acc[e] += xv * wr[e];
    }
#pragma unroll
    for (int e = 0; e < E_NUM; e++)
#pragma unroll
        for (int o = 16; o > 0; o >>= 1)
            acc[e] += __shfl_xor_sync(0xffffffffu, acc[e], o);

    if (lane == 0) {
        float s[E_NUM];
        float mx = -1e30f;
#pragma unroll
        for (int e = 0; e < E_NUM; e++) { s[e] = acc[e] + bg[e]; mx = fmaxf(mx, s[e]); }
        float sum = 0.f;
#pragma unroll
        for (int e = 0; e < E_NUM; e++) { s[e] = __expf(s[e] - mx); sum += s[e]; }
        float inv = 1.f / sum;
#pragma unroll
        for (int e = 0; e < E_NUM; e++) s[e] *= inv;

#pragma unroll
        for (int k = 0; k < K_TOP; k++) {
            int be = 0; float bv = -1.f;
#pragma unroll
            for (int e = 0; e < E_NUM; e++)
                if (s[e] > bv) { bv = s[e]; be = e; }
            s[be] = -2.f;
            int pos = atomicAdd(&g_count[be], 1);
            g_tok[be * B_TOK + pos] = b;
            g_te[b * K_TOP + k] = be;
            g_tp[b * K_TOP + k] = pos;
            g_tw[b * K_TOP + k] = bv;
        }
    }
}

// ---------------- kernels 2 & 3: grouped GEMM + bias + quickGELU ----------------
// MODE 1: A = gathered x rows (via g_tok), writes g_h.   K=1024, N=4096
// MODE 2: A = g_h rows (contiguous),      writes g_y.   K=4096, N=1024
template <int K, int N, int MODE>
__global__ __launch_bounds__(512, 1)
void ffn_gemm(const float* __restrict__ Ain,
              const float* __restrict__ W,      // [E, K, N]
              const float* __restrict__ bias)   // [E, N]
{
    constexpr int BM = 128, BN = 128, BK = 32;
    const int e = blockIdx.z;
    const int cnt = g_count[e];
    const int m0 = blockIdx.y * BM;
    if (m0 >= cnt) return;
    const int n0 = blockIdx.x * BN;

    __shared__ float As[BM][BK + 4];   // stride 36 floats -> conflict-free frag loads
    __shared__ float Bs[BK][BN + 8];   // stride 136 floats -> conflict-free frag loads
    __shared__ int rIdx[BM];

    const int tid = threadIdx.x;
    if (tid < BM) {
        int r = m0 + tid;
        rIdx[tid] = (r < cnt) ? ((MODE == 1) ? g_tok[e * B_TOK + r] : (e * B_TOK + r)) : -1;
    }
    __syncthreads();

    const float* Abase = (MODE == 1) ? Ain : (const float*)g_h;
    const float* Wp = W + (size_t)e * K * N;

    const int warp = tid >> 5, lane = tid & 31;
    const int mB = (warp >> 2) * 32;   // 4x4 warp grid over 128x128
    const int nB = (warp & 3) * 32;
    const int gr = lane >> 2, gc = lane & 3;

    float acc[2][4][4];
#pragma unroll
    for (int i = 0; i < 2; i++)
#pragma unroll
        for (int j = 0; j < 4; j++)
#pragma unroll
            for (int l = 0; l < 4; l++) acc[i][j][l] = 0.f;

    for (int k0 = 0; k0 < K; k0 += BK) {
        // stage A tile: 128x32 floats = 1024 float4, 2 per thread
#pragma unroll
        for (int i = 0; i < 2; i++) {
            int f = tid + i * 512;
            int r = f >> 3, c4 = (f & 7) << 2;
            int grow = rIdx[r];
            float4 v = make_float4(0.f, 0.f, 0.f, 0.f);
            if (grow >= 0)
                v = *reinterpret_cast<const float4*>(Abase + (size_t)grow * K + k0 + c4);
            As[r][c4 + 0] = __uint_as_float(f2tf32(v.x));
            As[r][c4 + 1] = __uint_as_float(f2tf32(v.y));
            As[r][c4 + 2] = __uint_as_float(f2tf32(v.z));
            As[r][c4 + 3] = __uint_as_float(f2tf32(v.w));
        }
        // stage B tile: 32x128 floats = 1024 float4, 2 per thread
#pragma unroll
        for (int i = 0; i < 2; i++) {
            int f = tid + i * 512;
            int r = f >> 5, c4 = (f & 31) << 2;
            float4 v = *reinterpret_cast<const float4*>(Wp + (size_t)(k0 + r) * N + n0 + c4);
            Bs[r][c4 + 0] = __uint_as_float(f2tf32(v.x));
            Bs[r][c4 + 1] = __uint_as_float(f2tf32(v.y));
            Bs[r][c4 + 2] = __uint_as_float(f2tf32(v.z));
            Bs[r][c4 + 3] = __uint_as_float(f2tf32(v.w));
        }
        __syncthreads();

#pragma unroll
        for (int kk = 0; kk < BK; kk += 8) {
            uint32_t af[2][4], bf[4][2];
#pragma unroll
            for (int mi = 0; mi < 2; mi++) {
                int r = mB + mi * 16 + gr;
                af[mi][0] = __float_as_uint(As[r][kk + gc]);
                af[mi][1] = __float_as_uint(As[r + 8][kk + gc]);
                af[mi][2] = __float_as_uint(As[r][kk + gc + 4]);
                af[mi][3] = __float_as_uint(As[r + 8][kk + gc + 4]);
            }
#pragma unroll
            for (int ni = 0; ni < 4; ni++) {
                int ccol = nB + ni * 8 + gr;
                bf[ni][0] = __float_as_uint(Bs[kk + gc][ccol]);
                bf[ni][1] = __float_as_uint(Bs[kk + gc + 4][ccol]);
            }
#pragma unroll
            for (int mi = 0; mi < 2; mi++)
#pragma unroll
                for (int ni = 0; ni < 4; ni++)
                    mma_tf32(acc[mi][ni], af[mi], bf[ni]);
        }
        __syncthreads();
    }

    // epilogue: +bias, quickGELU, store
    float* Outp = (MODE == 1) ? (float*)g_h : (float*)g_y;
    const float* bp = bias + (size_t)e * N;
#pragma unroll
    for (int mi = 0; mi < 2; mi++) {
#pragma unroll
        for (int half = 0; half < 2; half++) {
            int lr = mB + mi * 16 + gr + half * 8;
            int grow = m0 + lr;
            if (grow < cnt) {
                float* orow = Outp + ((size_t)e * B_TOK + grow) * N;
#pragma unroll
                for (int ni = 0; ni < 4; ni++) {
                    int col = n0 + nB + ni * 8 + gc * 2;
                    float v0 = acc[mi][ni][half * 2 + 0] + bp[col];
                    float v1 = acc[mi][ni][half * 2 + 1] + bp[col + 1];
                    v0 = quick_gelu(v0);
                    v1 = quick_gelu(v1);
                    *reinterpret_cast<float2*>(orow + col) = make_float2(v0, v1);
                }
            }
        }
    }
}

// ---------------- kernel 4: per-token LayerNorm + weighted combine ----------------
__global__ void combine_kernel(const float* __restrict__ ln_g,
                               const float* __restrict__ ln_b,
                               float* __restrict__ out) {
    const int b = blockIdx.x;
    const int tid = threadIdx.x;           // 256 threads, 4 cols each
    const int lane = tid & 31, warp = tid >> 5;
    __shared__ float red[16];
    float res[4] = {0.f, 0.f, 0.f, 0.f};

#pragma unroll
    for (int k = 0; k < K_TOP; k++) {
        int e = g_te[b * K_TOP + k];
        int pos = g_tp[b * K_TOP + k];
        float w = g_tw[b * K_TOP + k];
        const float* row = g_y + ((size_t)e * B_TOK + pos) * C_DIM;

        float v[4], s = 0.f, s2 = 0.f;
#pragma unroll
        for (int j = 0; j < 4; j++) {
            v[j] = row[tid + j * 256];
            s += v[j];
            s2 += v[j] * v[j];
        }
#pragma unroll
        for (int o = 16; o > 0; o >>= 1) {
            s  += __shfl_xor_sync(0xffffffffu, s, o);
            s2 += __shfl_xor_sync(0xffffffffu, s2, o);
        }
        if (lane == 0) { red[warp] = s; red[8 + warp] = s2; }
        __syncthreads();
        if (tid == 0) {
            float S = 0.f, S2 = 0.f;
#pragma unroll
            for (int i = 0; i < 8; i++) { S += red[i]; S2 += red[8 + i]; }
            red[0] = S; red[8] = S2;
        }
        __syncthreads();
        float mean = red[0] * (1.f / C_DIM);
        float var  = red[8] * (1.f / C_DIM) - mean * mean;
        float rs = rsqrtf(var + 1e-6f);
        const float* gp  = ln_g + e * C_DIM;
        const float* bp2 = ln_b + e * C_DIM;
#pragma unroll
        for (int j = 0; j < 4; j++) {
            int c = tid + j * 256;
            float nv = (v[j] - mean) * rs;
            res[j] += w * (nv * gp[c] + bp2[c]);
        }
        __syncthreads();
    }
#pragma unroll
    for (int j = 0; j < 4; j++)
        out[(size_t)b * C_DIM + tid + j * 256] = res[j];
}

// ---------------- launch ----------------
extern "C" void kernel_launch(void* const* d_in, const int* in_sizes, int n_in,
                              void* d_out, int out_size) {
    const float* x   = (const float*)d_in[0];
    const float* W1  = (const float*)d_in[1];
    const float* b1  = (const float*)d_in[2];
    const float* W2  = (const float*)d_in[3];
    const float* b2  = (const float*)d_in[4];
    const float* lng = (const float*)d_in[5];
    const float* lnb = (const float*)d_in[6];
    const float* Wg  = (const float*)d_in[7];
    const float* bg  = (const float*)d_in[8];
    float* out = (float*)d_out;

    zero_counts<<<1, 32>>>();
    gate_kernel<<<B_TOK / 8, 256>>>(x, Wg, bg);
    ffn_gemm<C_DIM, H_DIM, 1><<<dim3(H_DIM / 128, B_TOK / 128, E_NUM), 512>>>(x, W1, b1);
    ffn_gemm<H_DIM, C_DIM, 2><<<dim3(C_DIM / 128, B_TOK / 128, E_NUM), 512>>>(nullptr, W2, b2);
    combine_kernel<<<B_TOK, 256>>>(lng, lnb, out);
}

// round 4
// speedup vs baseline: 1.8530x; 1.8530x over previous
#include <cuda_runtime.h>
#include <cstdint>

#define B_TOK 8192
#define C_DIM 1024
#define E_NUM 8
#define K_TOP 4
#define H_DIM 4096

// ---------------- scratch (device globals; no allocations allowed) ----------------
__device__ int   g_count[E_NUM];
__device__ int   g_tok[E_NUM * B_TOK];
__device__ int   g_te[B_TOK * K_TOP];
__device__ int   g_tp[B_TOK * K_TOP];
__device__ float g_tw[B_TOK * K_TOP];
__device__ float g_h[(size_t)E_NUM * B_TOK * H_DIM];   // hidden acts, tf32 bits (1 GiB)
__device__ float g_y[(size_t)E_NUM * B_TOK * C_DIM];   // expert outputs pre-LN (256 MiB)
__device__ float g_xc [(size_t)B_TOK * C_DIM];         // x  as tf32 bits (32 MiB)
__device__ float g_w1c[(size_t)E_NUM * C_DIM * H_DIM]; // W1 as tf32 bits (128 MiB)
__device__ float g_w2c[(size_t)E_NUM * H_DIM * C_DIM]; // W2 as tf32 bits (128 MiB)

// ---------------- helpers ----------------
__device__ __forceinline__ uint32_t f2tf32(float f) {
    uint32_t u;
    asm("cvt.rna.tf32.f32 %0, %1;" : "=r"(u) : "f"(f));
    return u;
}

__device__ __forceinline__ void mma_tf32(float (&d)[4], const uint32_t (&a)[4], const uint32_t (&b)[2]) {
    asm volatile(
        "mma.sync.aligned.m16n8k8.row.col.f32.tf32.tf32.f32 "
        "{%0,%1,%2,%3}, {%4,%5,%6,%7}, {%8,%9}, {%0,%1,%2,%3};\n"
        : "+f"(d[0]), "+f"(d[1]), "+f"(d[2]), "+f"(d[3])
        : "r"(a[0]), "r"(a[1]), "r"(a[2]), "r"(a[3]), "r"(b[0]), "r"(b[1]));
}

__device__ __forceinline__ void cp16(uint32_t dst, const void* src, int sz) {
    asm volatile("cp.async.cg.shared.global [%0], [%1], 16, %2;"
                 :: "r"(dst), "l"(src), "r"(sz));
}

__device__ __forceinline__ float quick_gelu(float v) {
    return v / (1.f + __expf(-1.702f * v));
}

// ---------------- kernel 0: reset counters ----------------
__global__ void zero_counts() {
    if (threadIdx.x < E_NUM) g_count[threadIdx.x] = 0;
}

// ---------------- kernel 0b: tf32 pre-conversion ----------------
__global__ void convert_tf32(const float* __restrict__ src, int n4, int which) {
    float* dst = (which == 0) ? (float*)g_xc : (which == 1) ? (float*)g_w1c : (float*)g_w2c;
    int i = blockIdx.x * blockDim.x + threadIdx.x;
    int stride = gridDim.x * blockDim.x;
    for (; i < n4; i += stride) {
        float4 v = reinterpret_cast<const float4*>(src)[i];
        float4 o;
        o.x = __uint_as_float(f2tf32(v.x));
        o.y = __uint_as_float(f2tf32(v.y));
        o.z = __uint_as_float(f2tf32(v.z));
        o.w = __uint_as_float(f2tf32(v.w));
        reinterpret_cast<float4*>(dst)[i] = o;
    }
}

// ---------------- kernel 1: gating ----------------
__global__ void gate_kernel(const float* __restrict__ x,
                            const float* __restrict__ Wg,
                            const float* __restrict__ bg) {
    const int warp = threadIdx.x >> 5;
    const int lane = threadIdx.x & 31;
    const int b = blockIdx.x * 8 + warp;

    float acc[E_NUM];
#pragma unroll
    for (int e = 0; e < E_NUM; e++) acc[e] = 0.f;

    const float* xr = x + (size_t)b * C_DIM;
    for (int c = lane; c < C_DIM; c += 32) {
        float xv = xr[c];
        const float* wr = Wg + c * E_NUM;
#pragma unroll
        for (int e = 0; e < E_NUM; e++) acc[e] += xv * wr[e];
    }
#pragma unroll
    for (int e = 0; e < E_NUM; e++)
#pragma unroll
        for (int o = 16; o > 0; o >>= 1)
            acc[e] += __shfl_xor_sync(0xffffffffu, acc[e], o);

    if (lane == 0) {
        float s[E_NUM];
        float mx = -1e30f;
#pragma unroll
        for (int e = 0; e < E_NUM; e++) { s[e] = acc[e] + bg[e]; mx = fmaxf(mx, s[e]); }
        float sum = 0.f;
#pragma unroll
        for (int e = 0; e < E_NUM; e++) { s[e] = __expf(s[e] - mx); sum += s[e]; }
        float inv = 1.f / sum;
#pragma unroll
        for (int e = 0; e < E_NUM; e++) s[e] *= inv;

#pragma unroll
        for (int k = 0; k < K_TOP; k++) {
            int be = 0; float bv = -1.f;
#pragma unroll
            for (int e = 0; e < E_NUM; e++)
                if (s[e] > bv) { bv = s[e]; be = e; }
            s[be] = -2.f;
            int pos = atomicAdd(&g_count[be], 1);
            g_tok[be * B_TOK + pos] = b;
            g_te[b * K_TOP + k] = be;
            g_tp[b * K_TOP + k] = pos;
            g_tw[b * K_TOP + k] = bv;
        }
    }
}

// ---------------- kernels 2 & 3: cp.async-pipelined grouped GEMM ----------------
// MODE 1: A = gathered g_xc rows (via g_tok), W = g_w1c, writes g_h (tf32 bits). K=1024 N=4096
// MODE 2: A = g_h rows (contiguous),          W = g_w2c, writes g_y (fp32).      K=4096 N=1024
template <int K, int N, int MODE>
__global__ __launch_bounds__(512, 1)
void ffn_gemm(const float* __restrict__ bias)   // [E, N]
{
    constexpr int BM = 128, BN = 128, BK = 32, STAGES = 4;
    constexpr int ASTRIDE = 36, BSTRIDE = 136;
    constexpr int A_TILE = BM * ASTRIDE;
    constexpr int B_TILE = BK * BSTRIDE;
    constexpr int KT = K / BK;

    extern __shared__ float sm[];
    float* sA = sm;
    float* sB = sm + STAGES * A_TILE;
    __shared__ int rIdx[BM];

    const int e = blockIdx.z;
    const int cnt = g_count[e];
    const int m0 = blockIdx.y * BM;
    if (m0 >= cnt) return;
    const int n0 = blockIdx.x * BN;
    const int tid = threadIdx.x;

    if (tid < BM) {
        int r = m0 + tid;
        rIdx[tid] = (r < cnt) ? ((MODE == 1) ? g_tok[e * B_TOK + r] : (e * B_TOK + r)) : -1;
    }
    __syncthreads();

    const float* Abase = (MODE == 1) ? (const float*)g_xc : (const float*)g_h;
    const float* Wp = ((MODE == 1) ? (const float*)g_w1c : (const float*)g_w2c) + (size_t)e * K * N;

    const int rA = tid >> 3;
    const int cA = (tid & 7) << 2;
    const int rowA0 = rIdx[rA];
    const int rowA1 = rIdx[rA + 64];
    const float* pA0 = Abase + (size_t)(rowA0 < 0 ? 0 : rowA0) * K + cA;
    const float* pA1 = Abase + (size_t)(rowA1 < 0 ? 0 : rowA1) * K + cA;
    const int szA0 = rowA0 >= 0 ? 16 : 0;
    const int szA1 = rowA1 >= 0 ? 16 : 0;

    const int rB = tid >> 5;
    const int cB = (tid & 31) << 2;
    const float* pB = Wp + (size_t)rB * N + n0 + cB;

    const uint32_t saddrA = (uint32_t)__cvta_generic_to_shared(sA);
    const uint32_t saddrB = (uint32_t)__cvta_generic_to_shared(sB);
    const uint32_t dA0 = saddrA + (uint32_t)(rA * ASTRIDE + cA) * 4u;
    const uint32_t dA1 = saddrA + (uint32_t)((rA + 64) * ASTRIDE + cA) * 4u;
    const uint32_t dB0 = saddrB + (uint32_t)(rB * BSTRIDE + cB) * 4u;
    const uint32_t dB1 = saddrB + (uint32_t)((rB + 16) * BSTRIDE + cB) * 4u;

#define LOAD_TILE(slot, k0)                                                        \
    do {                                                                           \
        uint32_t aoff = (uint32_t)(slot) * (A_TILE * 4u);                          \
        uint32_t boff = (uint32_t)(slot) * (B_TILE * 4u);                          \
        cp16(dA0 + aoff, pA0 + (k0), szA0);                                        \
        cp16(dA1 + aoff, pA1 + (k0), szA1);                                        \
        cp16(dB0 + boff, pB + (size_t)(k0) * N, 16);                               \
        cp16(dB1 + boff, pB + (size_t)((k0) + 16) * N, 16);                        \
    } while (0)

#pragma unroll
    for (int s = 0; s < STAGES - 1; s++) {
        LOAD_TILE(s, s * BK);
        asm volatile("cp.async.commit_group;");
    }

    const int warp = tid >> 5, lane = tid & 31;
    const int mB = (warp >> 2) * 32;
    const int nB = (warp & 3) * 32;
    const int gr = lane >> 2, gc = lane & 3;

    float acc[2][4][4];
#pragma unroll
    for (int i = 0; i < 2; i++)
#pragma unroll
        for (int j = 0; j < 4; j++)
#pragma unroll
            for (int l = 0; l < 4; l++) acc[i][j][l] = 0.f;

    for (int kt = 0; kt < KT; kt++) {
        asm volatile("cp.async.wait_group %0;" :: "n"(STAGES - 2));
        __syncthreads();

        int kload = kt + STAGES - 1;
        if (kload < KT) LOAD_TILE(kload & (STAGES - 1), kload * BK);
        asm volatile("cp.async.commit_group;");

        const float* As = sA + (kt & (STAGES - 1)) * A_TILE;
        const float* Bs = sB + (kt & (STAGES - 1)) * B_TILE;

#pragma unroll
        for (int kk = 0; kk < BK; kk += 8) {
            uint32_t af[2][4], bf[4][2];
#pragma unroll
            for (int mi = 0; mi < 2; mi++) {
                int r = mB + mi * 16 + gr;
                af[mi][0] = __float_as_uint(As[r * ASTRIDE + kk + gc]);
                af[mi][1] = __float_as_uint(As[(r + 8) * ASTRIDE + kk + gc]);
                af[mi][2] = __float_as_uint(As[r * ASTRIDE + kk + gc + 4]);
                af[mi][3] = __float_as_uint(As[(r + 8) * ASTRIDE + kk + gc + 4]);
            }
#pragma unroll
            for (int ni = 0; ni < 4; ni++) {
                int ccol = nB + ni * 8 + gr;
                bf[ni][0] = __float_as_uint(Bs[(kk + gc) * BSTRIDE + ccol]);
                bf[ni][1] = __float_as_uint(Bs[(kk + gc + 4) * BSTRIDE + ccol]);
            }
#pragma unroll
            for (int mi = 0; mi < 2; mi++)
#pragma unroll
                for (int ni = 0; ni < 4; ni++)
                    mma_tf32(acc[mi][ni], af[mi], bf[ni]);
        }
    }
#undef LOAD_TILE

    float* Outp = (MODE == 1) ? (float*)g_h : (float*)g_y;
    const float* bp = bias + (size_t)e * N;
#pragma unroll
    for (int mi = 0; mi < 2; mi++) {
#pragma unroll
        for (int half = 0; half < 2; half++) {
            int lr = mB + mi * 16 + gr + half * 8;
            int grow = m0 + lr;
            if (grow < cnt) {
                float* orow = Outp + ((size_t)e * B_TOK + grow) * N;
#pragma unroll
                for (int ni = 0; ni < 4; ni++) {
                    int col = n0 + nB + ni * 8 + gc * 2;
                    float v0 = quick_gelu(acc[mi][ni][half * 2 + 0] + bp[col]);
                    float v1 = quick_gelu(acc[mi][ni][half * 2 + 1] + bp[col + 1]);
                    if (MODE == 1) {
                        v0 = __uint_as_float(f2tf32(v0));
                        v1 = __uint_as_float(f2tf32(v1));
                    }
                    *reinterpret_cast<float2*>(orow + col) = make_float2(v0, v1);
                }
            }
        }
    }
}

// ---------------- kernel 4: per-token LayerNorm + weighted combine ----------------
__global__ void combine_kernel(const float* __restrict__ ln_g,
                               const float* __restrict__ ln_b,
                               float* __restrict__ out) {
    const int b = blockIdx.x;
    const int tid = threadIdx.x;
    const int lane = tid & 31, warp = tid >> 5;
    __shared__ float red[16];
    float res[4] = {0.f, 0.f, 0.f, 0.f};

#pragma unroll
    for (int k = 0; k < K_TOP; k++) {
        int e = g_te[b * K_TOP + k];
        int pos = g_tp[b * K_TOP + k];
        float w = g_tw[b * K_TOP + k];
        const float* row = g_y + ((size_t)e * B_TOK + pos) * C_DIM;

        float v[4], s = 0.f, s2 = 0.f;
#pragma unroll
        for (int j = 0; j < 4; j++) {
            v[j] = row[tid + j * 256];
            s += v[j];
            s2 += v[j] * v[j];
        }
#pragma unroll
        for (int o = 16; o > 0; o >>= 1) {
            s  += __shfl_xor_sync(0xffffffffu, s, o);
            s2 += __shfl_xor_sync(0xffffffffu, s2, o);
        }
        if (lane == 0) { red[warp] = s; red[8 + warp] = s2; }
        __syncthreads();
        if (tid == 0) {
            float S = 0.f, S2 = 0.f;
#pragma unroll
            for (int i = 0; i < 8; i++) { S += red[i]; S2 += red[8 + i]; }
            red[0] = S; red[8] = S2;
        }
        __syncthreads();
        float mean = red[0] * (1.f / C_DIM);
        float var  = red[8] * (1.f / C_DIM) - mean * mean;
        float rs = rsqrtf(var + 1e-6f);
        const float* gp  = ln_g + e * C_DIM;
        const float* bp2 = ln_b + e * C_DIM;
#pragma unroll
        for (int j = 0; j < 4; j++) {
            int c = tid + j * 256;
            float nv = (v[j] - mean) * rs;
            res[j] += w * (nv * gp[c] + bp2[c]);
        }
        __syncthreads();
    }
#pragma unroll
    for (int j = 0; j < 4; j++)
        out[(size_t)b * C_DIM + tid + j * 256] = res[j];
}

// ---------------- launch ----------------
extern "C" void kernel_launch(void* const* d_in, const int* in_sizes, int n_in,
                              void* d_out, int out_size) {
    const float* x   = (const float*)d_in[0];
    const float* W1  = (const float*)d_in[1];
    const float* b1  = (const float*)d_in[2];
    const float* W2  = (const float*)d_in[3];
    const float* b2  = (const float*)d_in[4];
    const float* lng = (const float*)d_in[5];
    const float* lnb = (const float*)d_in[6];
    const float* Wg  = (const float*)d_in[7];
    const float* bg  = (const float*)d_in[8];
    float* out = (float*)d_out;

    constexpr int SMEM_BYTES = 4 * (128 * 36 + 32 * 136) * 4;   // 143360

    cudaFuncSetAttribute(ffn_gemm<C_DIM, H_DIM, 1>,
                         cudaFuncAttributeMaxDynamicSharedMemorySize, SMEM_BYTES);
    cudaFuncSetAttribute(ffn_gemm<H_DIM, C_DIM, 2>,
                         cudaFuncAttributeMaxDynamicSharedMemorySize, SMEM_BYTES);

    zero_counts<<<1, 32>>>();
    convert_tf32<<<1024, 256>>>(x,  (B_TOK * C_DIM) / 4, 0);
    convert_tf32<<<2048, 256>>>(W1, (E_NUM * C_DIM * H_DIM) / 4, 1);
    convert_tf32<<<2048, 256>>>(W2, (E_NUM * H_DIM * C_DIM) / 4, 2);
    gate_kernel<<<B_TOK / 8, 256>>>(x, Wg, bg);
    ffn_gemm<C_DIM, H_DIM, 1><<<dim3(H_DIM / 128, B_TOK / 128, E_NUM), 512, SMEM_BYTES>>>(b1);
    ffn_gemm<H_DIM, C_DIM, 2><<<dim3(C_DIM / 128, B_TOK / 128, E_NUM), 512, SMEM_BYTES>>>(b2);
    combine_kernel<<<B_TOK, 256>>>(lng, lnb, out);
}

// round 8
// speedup vs baseline: 2.1827x; 1.1779x over previous
#include <cuda_runtime.h>
#include <cstdint>

#define B_TOK 8192
#define C_DIM 1024
#define E_NUM 8
#define K_TOP 4
#define H_DIM 4096

// ---------------- scratch (device globals; no allocations allowed) ----------------
__device__ int   g_count[E_NUM];
__device__ int   g_tok[E_NUM * B_TOK];
__device__ int   g_te[B_TOK * K_TOP];
__device__ int   g_tp[B_TOK * K_TOP];
__device__ float g_tw[B_TOK * K_TOP];
__device__ float g_h[(size_t)E_NUM * B_TOK * H_DIM];   // hidden acts, tf32 bits (1 GiB)
__device__ float g_y[(size_t)E_NUM * B_TOK * C_DIM];   // expert outputs pre-LN (256 MiB)
__device__ float g_xc [(size_t)B_TOK * C_DIM];         // x  as tf32 bits
__device__ float g_w1c[(size_t)E_NUM * C_DIM * H_DIM]; // W1 as tf32 bits [e][K][N]
__device__ float g_w2c[(size_t)E_NUM * H_DIM * C_DIM]; // W2 as tf32 bits [e][K][N]

// ---------------- helpers ----------------
__device__ __forceinline__ uint32_t f2tf32(float f) {
    uint32_t u;
    asm("cvt.rna.tf32.f32 %0, %1;" : "=r"(u) : "f"(f));
    return u;
}

__device__ __forceinline__ void mma_tf32(float (&d)[4], const uint32_t (&a)[4], const uint32_t (&b)[2]) {
    asm volatile(
        "mma.sync.aligned.m16n8k8.row.col.f32.tf32.tf32.f32 "
        "{%0,%1,%2,%3}, {%4,%5,%6,%7}, {%8,%9}, {%0,%1,%2,%3};\n"
        : "+f"(d[0]), "+f"(d[1]), "+f"(d[2]), "+f"(d[3])
        : "r"(a[0]), "r"(a[1]), "r"(a[2]), "r"(a[3]), "r"(b[0]), "r"(b[1]));
}

__device__ __forceinline__ void cp16(uint32_t dst, const void* src, int sz) {
    asm volatile("cp.async.cg.shared.global [%0], [%1], 16, %2;"
                 :: "r"(dst), "l"(src), "r"(sz));
}

__device__ __forceinline__ float quick_gelu(float v) {
    return v / (1.f + __expf(-1.702f * v));
}

// ---------------- kernel 0: reset counters ----------------
__global__ void zero_counts() {
    if (threadIdx.x < E_NUM) g_count[threadIdx.x] = 0;
}

// ---------------- kernel 0b: tf32 pre-conversion ----------------
__global__ void convert_tf32(const float* __restrict__ src, int n4, int which) {
    float* dst = (which == 0) ? (float*)g_xc : (which == 1) ? (float*)g_w1c : (float*)g_w2c;
    int i = blockIdx.x * blockDim.x + threadIdx.x;
    int stride = gridDim.x * blockDim.x;
    for (; i < n4; i += stride) {
        float4 v = reinterpret_cast<const float4*>(src)[i];
        float4 o;
        o.x = __uint_as_float(f2tf32(v.x));
        o.y = __uint_as_float(f2tf32(v.y));
        o.z = __uint_as_float(f2tf32(v.z));
        o.w = __uint_as_float(f2tf32(v.w));
        reinterpret_cast<float4*>(dst)[i] = o;
    }
}

// ---------------- kernel 1: gating ----------------
__global__ void gate_kernel(const float* __restrict__ x,
                            const float* __restrict__ Wg,
                            const float* __restrict__ bg) {
    const int warp = threadIdx.x >> 5;
    const int lane = threadIdx.x & 31;
    const int b = blockIdx.x * 8 + warp;

    float acc[E_NUM];
#pragma unroll
    for (int e = 0; e < E_NUM; e++) acc[e] = 0.f;

    const float* xr = x + (size_t)b * C_DIM;
    for (int c = lane; c < C_DIM; c += 32) {
        float xv = xr[c];
        const float* wr = Wg + c * E_NUM;
#pragma unroll
        for (int e = 0; e < E_NUM; e++) acc[e] += xv * wr[e];
    }
#pragma unroll
    for (int e = 0; e < E_NUM; e++)
#pragma unroll
        for (int o = 16; o > 0; o >>= 1)
            acc[e] += __shfl_xor_sync(0xffffffffu, acc[e], o);

    if (lane == 0) {
        float s[E_NUM];
        float mx = -1e30f;
#pragma unroll
        for (int e = 0; e < E_NUM; e++) { s[e] = acc[e] + bg[e]; mx = fmaxf(mx, s[e]); }
        float sum = 0.f;
#pragma unroll
        for (int e = 0; e < E_NUM; e++) { s[e] = __expf(s[e] - mx); sum += s[e]; }
        float inv = 1.f / sum;
#pragma unroll
        for (int e = 0; e < E_NUM; e++) s[e] *= inv;

#pragma unroll
        for (int k = 0; k < K_TOP; k++) {
            int be = 0; float bv = -1.f;
#pragma unroll
            for (int e = 0; e < E_NUM; e++)
                if (s[e] > bv) { bv = s[e]; be = e; }
            s[be] = -2.f;
            int pos = atomicAdd(&g_count[be], 1);
            g_tok[be * B_TOK + pos] = b;
            g_te[b * K_TOP + k] = be;
            g_tp[b * K_TOP + k] = pos;
            g_tw[b * K_TOP + k] = bv;
        }
    }
}

// ---------------- kernels 2 & 3: cp.async-pipelined grouped GEMM ----------------
// CTA tile 128(M) x 256(N), 256 threads = 8 warps (2m x 4n), warp tile 64x64.
// MODE 1: A = gathered g_xc rows (via g_tok), W = g_w1c, writes g_h (tf32 bits). K=1024 N=4096
// MODE 2: A = g_h rows (contiguous),          W = g_w2c, writes g_y (fp32).      K=4096 N=1024
template <int K, int N, int MODE>
__global__ __launch_bounds__(256, 1)
void ffn_gemm(const float* __restrict__ bias)   // [E, N]
{
    constexpr int BM = 128, BN = 256, BK = 32, STAGES = 3;
    constexpr int ASTRIDE = 36;                  // floats (144 B rows)
    constexpr int BSTRIDE = BN + 8;              // 264 floats (1056 B rows)
    constexpr int A_TILE = BM * ASTRIDE;         // 4608 floats
    constexpr int B_TILE = BK * BSTRIDE;         // 8448 floats
    constexpr int STAGE_FLOATS = A_TILE + B_TILE;
    constexpr int KT = K / BK;

    extern __shared__ float sm[];
    __shared__ int rIdx[BM];

    const int e = blockIdx.z;
    const int cnt = g_count[e];
    const int m0 = blockIdx.y * BM;
    if (m0 >= cnt) return;
    const int n0 = blockIdx.x * BN;
    const int tid = threadIdx.x;

    if (tid < BM) {
        int r = m0 + tid;
        rIdx[tid] = (r < cnt) ? ((MODE == 1) ? g_tok[e * B_TOK + r] : (e * B_TOK + r)) : -1;
    }
    __syncthreads();

    const float* Abase = (MODE == 1) ? (const float*)g_xc : (const float*)g_h;
    const float* Wp = ((MODE == 1) ? (const float*)g_w1c : (const float*)g_w2c) + (size_t)e * K * N;

    // ---- staging plan: 12 x 16B chunks per thread per stage (A: 4, B: 8) ----
    const uint32_t saddr = (uint32_t)__cvta_generic_to_shared(sm);
    const float* srcA[4];
    uint32_t dstA[4];
    int szA[4];
#pragma unroll
    for (int u = 0; u < 4; u++) {
        int idx = tid + u * 256;              // 0..1023
        int row = idx >> 3, c16 = idx & 7;    // row<128, 8 chunks of 16B per row
        dstA[u] = saddr + (uint32_t)(row * ASTRIDE + c16 * 4) * 4u;
        int gr = rIdx[row];
        srcA[u] = Abase + (size_t)(gr < 0 ? 0 : gr) * K + c16 * 4;
        szA[u] = (gr < 0) ? 0 : 16;
    }
    const float* srcB[8];
    uint32_t dstB[8];
#pragma unroll
    for (int u = 0; u < 8; u++) {
        int idx = tid + u * 256;              // 0..2047
        int r = idx >> 6, c16 = idx & 63;     // r<32, 64 chunks of 16B per row
        dstB[u] = saddr + (uint32_t)(A_TILE + r * BSTRIDE + c16 * 4) * 4u;
        srcB[u] = Wp + (size_t)r * N + n0 + c16 * 4;
    }

#define LOAD_TILE(slot, k0)                                                      \
    do {                                                                         \
        uint32_t so = (uint32_t)(slot) * (STAGE_FLOATS * 4u);                    \
        _Pragma("unroll")                                                        \
        for (int u = 0; u < 4; u++) cp16(dstA[u] + so, srcA[u] + (k0), szA[u]);  \
        _Pragma("unroll")                                                        \
        for (int u = 0; u < 8; u++)                                              \
            cp16(dstB[u] + so, srcB[u] + (size_t)(k0) * N, 16);                  \
    } while (0)

#pragma unroll
    for (int s = 0; s < STAGES - 1; s++) {
        LOAD_TILE(s, s * BK);
        asm volatile("cp.async.commit_group;");
    }

    const int warp = tid >> 5, lane = tid & 31;
    const int mB = (warp >> 2) * 64;          // 2 m-warps
    const int nB = (warp & 3) * 64;           // 4 n-warps
    const int gr = lane >> 2, gc = lane & 3;

    float acc[4][8][4];
#pragma unroll
    for (int i = 0; i < 4; i++)
#pragma unroll
        for (int j = 0; j < 8; j++)
#pragma unroll
            for (int l = 0; l < 4; l++) acc[i][j][l] = 0.f;

    int slot = 0;
    for (int kt = 0; kt < KT; kt++) {
        asm volatile("cp.async.wait_group %0;" :: "n"(STAGES - 2));
        __syncthreads();

        int kload = kt + STAGES - 1;
        if (kload < KT) {
            int ls = kload - STAGES * (kload / STAGES);   // kload % 3
            LOAD_TILE(ls, kload * BK);
        }
        asm volatile("cp.async.commit_group;");

        const float* As = sm + slot * STAGE_FLOATS;
        const float* Bs = As + A_TILE;
        slot = (slot == STAGES - 1) ? 0 : slot + 1;

#pragma unroll
        for (int kk = 0; kk < BK; kk += 8) {
            uint32_t af[4][4], bf[8][2];
#pragma unroll
            for (int mi = 0; mi < 4; mi++) {
                int r = mB + mi * 16 + gr;
                af[mi][0] = __float_as_uint(As[r * ASTRIDE + kk + gc]);
                af[mi][1] = __float_as_uint(As[(r + 8) * ASTRIDE + kk + gc]);
                af[mi][2] = __float_as_uint(As[r * ASTRIDE + kk + gc + 4]);
                af[mi][3] = __float_as_uint(As[(r + 8) * ASTRIDE + kk + gc + 4]);
            }
#pragma unroll
            for (int ni = 0; ni < 8; ni++) {
                int ccol = nB + ni * 8 + gr;
                bf[ni][0] = __float_as_uint(Bs[(kk + gc) * BSTRIDE + ccol]);
                bf[ni][1] = __float_as_uint(Bs[(kk + gc + 4) * BSTRIDE + ccol]);
            }
#pragma unroll
            for (int mi = 0; mi < 4; mi++)
#pragma unroll
                for (int ni = 0; ni < 8; ni++)
                    mma_tf32(acc[mi][ni], af[mi], bf[ni]);
        }
    }
#undef LOAD_TILE

    // ---- epilogue: +bias, quickGELU, store ----
    float* Outp = (MODE == 1) ? (float*)g_h : (float*)g_y;
    const float* bp = bias + (size_t)e * N;
#pragma unroll
    for (int mi = 0; mi < 4; mi++) {
#pragma unroll
        for (int half = 0; half < 2; half++) {
            int lr = mB + mi * 16 + gr + half * 8;
            int grow = m0 + lr;
            if (grow < cnt) {
                float* orow = Outp + ((size_t)e * B_TOK + grow) * N;
#pragma unroll
                for (int ni = 0; ni < 8; ni++) {
                    int col = n0 + nB + ni * 8 + gc * 2;
                    float v0 = quick_gelu(acc[mi][ni][half * 2 + 0] + bp[col]);
                    float v1 = quick_gelu(acc[mi][ni][half * 2 + 1] + bp[col + 1]);
                    if (MODE == 1) {
                        v0 = __uint_as_float(f2tf32(v0));
                        v1 = __uint_as_float(f2tf32(v1));
                    }
                    *reinterpret_cast<float2*>(orow + col) = make_float2(v0, v1);
                }
            }
        }
    }
}

// ---------------- kernel 4: per-token LayerNorm + weighted combine ----------------
__global__ void combine_kernel(const float* __restrict__ ln_g,
                               const float* __restrict__ ln_b,
                               float* __restrict__ out) {
    const int b = blockIdx.x;
    const int tid = threadIdx.x;
    const int lane = tid & 31, warp = tid >> 5;
    __shared__ float red[16];
    float res[4] = {0.f, 0.f, 0.f, 0.f};

#pragma unroll
    for (int k = 0; k < K_TOP; k++) {
        int e = g_te[b * K_TOP + k];
        int pos = g_tp[b * K_TOP + k];
        float w = g_tw[b * K_TOP + k];
        const float* row = g_y + ((size_t)e * B_TOK + pos) * C_DIM;

        float v[4], s = 0.f, s2 = 0.f;
#pragma unroll
        for (int j = 0; j < 4; j++) {
            v[j] = row[tid + j * 256];
            s += v[j];
            s2 += v[j] * v[j];
        }
#pragma unroll
        for (int o = 16; o > 0; o >>= 1) {
            s  += __shfl_xor_sync(0xffffffffu, s, o);
            s2 += __shfl_xor_sync(0xffffffffu, s2, o);
        }
        if (lane == 0) { red[warp] = s; red[8 + warp] = s2; }
        __syncthreads();
        if (tid == 0) {
            float S = 0.f, S2 = 0.f;
#pragma unroll
            for (int i = 0; i < 8; i++) { S += red[i]; S2 += red[8 + i]; }
            red[0] = S; red[8] = S2;
        }
        __syncthreads();
        float mean = red[0] * (1.f / C_DIM);
        float var  = red[8] * (1.f / C_DIM) - mean * mean;
        float rs = rsqrtf(var + 1e-6f);
        const float* gp  = ln_g + e * C_DIM;
        const float* bp2 = ln_b + e * C_DIM;
#pragma unroll
        for (int j = 0; j < 4; j++) {
            int c = tid + j * 256;
            float nv = (v[j] - mean) * rs;
            res[j] += w * (nv * gp[c] + bp2[c]);
        }
        __syncthreads();
    }
#pragma unroll
    for (int j = 0; j < 4; j++)
        out[(size_t)b * C_DIM + tid + j * 256] = res[j];
}

// ---------------- launch ----------------
extern "C" void kernel_launch(void* const* d_in, const int* in_sizes, int n_in,
                              void* d_out, int out_size) {
    const float* x   = (const float*)d_in[0];
    const float* W1  = (const float*)d_in[1];
    const float* b1  = (const float*)d_in[2];
    const float* W2  = (const float*)d_in[3];
    const float* b2  = (const float*)d_in[4];
    const float* lng = (const float*)d_in[5];
    const float* lnb = (const float*)d_in[6];
    const float* Wg  = (const float*)d_in[7];
    const float* bg  = (const float*)d_in[8];
    float* out = (float*)d_out;

    constexpr int SMEM_BYTES = 3 * (128 * 36 + 32 * 264) * 4;   // 156672

    cudaFuncSetAttribute(ffn_gemm<C_DIM, H_DIM, 1>,
                         cudaFuncAttributeMaxDynamicSharedMemorySize, SMEM_BYTES);
    cudaFuncSetAttribute(ffn_gemm<H_DIM, C_DIM, 2>,
                         cudaFuncAttributeMaxDynamicSharedMemorySize, SMEM_BYTES);

    zero_counts<<<1, 32>>>();
    convert_tf32<<<1024, 256>>>(x,  (B_TOK * C_DIM) / 4, 0);
    convert_tf32<<<2048, 256>>>(W1, (E_NUM * C_DIM * H_DIM) / 4, 1);
    convert_tf32<<<2048, 256>>>(W2, (E_NUM * H_DIM * C_DIM) / 4, 2);
    gate_kernel<<<B_TOK / 8, 256>>>(x, Wg, bg);
    ffn_gemm<C_DIM, H_DIM, 1><<<dim3(H_DIM / 256, B_TOK / 128, E_NUM), 256, SMEM_BYTES>>>(b1);
    ffn_gemm<H_DIM, C_DIM, 2><<<dim3(C_DIM / 256, B_TOK / 128, E_NUM), 256, SMEM_BYTES>>>(b2);
    combine_kernel<<<B_TOK, 256>>>(lng, lnb, out);
}

// round 10
// speedup vs baseline: 3.5668x; 1.6341x over previous
#include <cuda_runtime.h>
#include <cuda_fp16.h>
#include <cstdint>

#define B_TOK 8192
#define C_DIM 1024
#define E_NUM 8
#define K_TOP 4
#define H_DIM 4096

// ---------------- scratch (device globals; no allocations allowed) ----------------
__device__ int    g_count[E_NUM];
__device__ int    g_tok[E_NUM * B_TOK];
__device__ int    g_te[B_TOK * K_TOP];
__device__ int    g_tp[B_TOK * K_TOP];
__device__ float  g_tw[B_TOK * K_TOP];
__device__ __half g_h[(size_t)E_NUM * B_TOK * H_DIM];    // hidden acts, half (512 MiB)
__device__ float  g_y[(size_t)E_NUM * B_TOK * C_DIM];    // expert outputs pre-LN (fp32)
__device__ __half g_xc [(size_t)B_TOK * C_DIM];          // x as half [b][C]
__device__ __half g_w1t[(size_t)E_NUM * H_DIM * C_DIM];  // W1^T: [e][n=H][k=C] half
__device__ __half g_w2t[(size_t)E_NUM * C_DIM * H_DIM];  // W2^T: [e][n=C][k=H] half

// ---------------- helpers ----------------
__device__ __forceinline__ void mma_f16(float (&d)[4], const uint32_t (&a)[4], const uint32_t (&b)[2]) {
    asm volatile(
        "mma.sync.aligned.m16n8k16.row.col.f32.f16.f16.f32 "
        "{%0,%1,%2,%3}, {%4,%5,%6,%7}, {%8,%9}, {%0,%1,%2,%3};\n"
        : "+f"(d[0]), "+f"(d[1]), "+f"(d[2]), "+f"(d[3])
        : "r"(a[0]), "r"(a[1]), "r"(a[2]), "r"(a[3]), "r"(b[0]), "r"(b[1]));
}

__device__ __forceinline__ void cp16(uint32_t dst, const void* src, int sz) {
    asm volatile("cp.async.cg.shared.global [%0], [%1], 16, %2;"
                 :: "r"(dst), "l"(src), "r"(sz));
}

__device__ __forceinline__ float quick_gelu(float v) {
    return v / (1.f + __expf(-1.702f * v));
}

// ---------------- kernel 0: reset counters ----------------
__global__ void zero_counts() {
    if (threadIdx.x < E_NUM) g_count[threadIdx.x] = 0;
}

// ---------------- kernel 0a: x -> half ----------------
__global__ void convert_x_half(const float* __restrict__ src, int n4) {
    uint2* dst = (uint2*)g_xc;
    int i = blockIdx.x * blockDim.x + threadIdx.x;
    int stride = gridDim.x * blockDim.x;
    for (; i < n4; i += stride) {
        float4 v = reinterpret_cast<const float4*>(src)[i];
        __half2 h01 = __floats2half2_rn(v.x, v.y);
        __half2 h23 = __floats2half2_rn(v.z, v.w);
        uint2 o;
        o.x = *reinterpret_cast<uint32_t*>(&h01);
        o.y = *reinterpret_cast<uint32_t*>(&h23);
        dst[i] = o;
    }
}

// ---------------- kernel 0b: transpose + half convert of weights ----------------
// in: [e][KK][NN] fp32 -> out: [e][NN][KK] half
template <int KK, int NN>
__global__ void transpose_half(const float* __restrict__ src, __half* __restrict__ dst) {
    __shared__ float t[32][33];
    const int e = blockIdx.z;
    const float* in = src + (size_t)e * KK * NN;
    __half* out = dst + (size_t)e * NN * KK;
    const int tx = threadIdx.x, ty = threadIdx.y;    // (32, 8)
    const int k0 = blockIdx.x * 32, n0 = blockIdx.y * 32;
#pragma unroll
    for (int i = 0; i < 4; i++) {
        int k = k0 + ty + i * 8;
        t[ty + i * 8][tx] = in[(size_t)k * NN + n0 + tx];
    }
    __syncthreads();
#pragma unroll
    for (int i = 0; i < 4; i++) {
        int n = n0 + ty + i * 8;
        out[(size_t)n * KK + k0 + tx] = __float2half(t[tx][ty + i * 8]);
    }
}

// ---------------- kernel 1: gating (fp32) ----------------
__global__ void gate_kernel(const float* __restrict__ x,
                            const float* __restrict__ Wg,
                            const float* __restrict__ bg) {
    const int warp = threadIdx.x >> 5;
    const int lane = threadIdx.x & 31;
    const int b = blockIdx.x * 8 + warp;

    float acc[E_NUM];
#pragma unroll
    for (int e = 0; e < E_NUM; e++) acc[e] = 0.f;

    const float* xr = x + (size_t)b * C_DIM;
    for (int c = lane; c < C_DIM; c += 32) {
        float xv = xr[c];
        const float* wr = Wg + c * E_NUM;
#pragma unroll
        for (int e = 0; e < E_NUM; e++) acc[e] += xv * wr[e];
    }
#pragma unroll
    for (int e = 0; e < E_NUM; e++)
#pragma unroll
        for (int o = 16; o > 0; o >>= 1)
            acc[e] += __shfl_xor_sync(0xffffffffu, acc[e], o);

    if (lane == 0) {
        float s[E_NUM];
        float mx = -1e30f;
#pragma unroll
        for (int e = 0; e < E_NUM; e++) { s[e] = acc[e] + bg[e]; mx = fmaxf(mx, s[e]); }
        float sum = 0.f;
#pragma unroll
        for (int e = 0; e < E_NUM; e++) { s[e] = __expf(s[e] - mx); sum += s[e]; }
        float inv = 1.f / sum;
#pragma unroll
        for (int e = 0; e < E_NUM; e++) s[e] *= inv;

#pragma unroll
        for (int k = 0; k < K_TOP; k++) {
            int be = 0; float bv = -1.f;
#pragma unroll
            for (int e = 0; e < E_NUM; e++)
                if (s[e] > bv) { bv = s[e]; be = e; }
            s[be] = -2.f;
            int pos = atomicAdd(&g_count[be], 1);
            g_tok[be * B_TOK + pos] = b;
            g_te[b * K_TOP + k] = be;
            g_tp[b * K_TOP + k] = pos;
            g_tw[b * K_TOP + k] = bv;
        }
    }
}

// ---------------- kernels 2 & 3: fp16 cp.async-pipelined grouped GEMM ----------------
// CTA tile 128(M) x 256(N), 256 threads = 8 warps (2m x 4n), warp tile 64x64.
// A smem: [128][72] half (k-major). B smem: [256][72] half (k-major, from W^T).
// MODE 1: A = gathered g_xc rows, B = g_w1t, out g_h (half).  K=1024 N=4096
// MODE 2: A = g_h rows,           B = g_w2t, out g_y (fp32).  K=4096 N=1024
template <int K, int N, int MODE>
__global__ __launch_bounds__(256, 1)
void ffn_gemm(const float* __restrict__ bias)   // [E, N]
{
    constexpr int BM = 128, BN = 256, BK = 64, STAGES = 3;
    constexpr int STRH = 72;                          // halfs per smem row
    constexpr int A_BYTES = BM * STRH * 2;            // 18432
    constexpr int B_BYTES = BN * STRH * 2;            // 36864
    constexpr int STAGE_BYTES = A_BYTES + B_BYTES;    // 55296
    constexpr int KT = K / BK;

    extern __shared__ char sm[];
    __shared__ int rIdx[BM];

    const int e = blockIdx.z;
    const int cnt = g_count[e];
    const int m0 = blockIdx.y * BM;
    if (m0 >= cnt) return;
    const int n0 = blockIdx.x * BN;
    const int tid = threadIdx.x;

    if (tid < BM) {
        int r = m0 + tid;
        rIdx[tid] = (r < cnt) ? ((MODE == 1) ? g_tok[e * B_TOK + r] : (e * B_TOK + r)) : -1;
    }
    __syncthreads();

    const __half* Abase = (MODE == 1) ? (const __half*)g_xc : (const __half*)g_h;
    const __half* Wt = ((MODE == 1) ? (const __half*)g_w1t : (const __half*)g_w2t)
                       + (size_t)e * (size_t)K * N;   // [N][K]

    // ---- staging plan per stage: A 4 chunks + B 8 chunks of 16B per thread ----
    const uint32_t saddr = (uint32_t)__cvta_generic_to_shared(sm);
    const __half* srcA[4];
    uint32_t dstA[4];
    int szA[4];
#pragma unroll
    for (int u = 0; u < 4; u++) {
        int idx = tid + u * 256;              // 0..1023
        int row = idx >> 3, c8 = (idx & 7) * 8;    // 8 chunks of 8 halfs per row
        dstA[u] = saddr + (uint32_t)(row * STRH + c8) * 2u;
        int gr = rIdx[row];
        srcA[u] = Abase + (size_t)(gr < 0 ? 0 : gr) * K + c8;
        szA[u] = (gr < 0) ? 0 : 16;
    }
    const __half* srcB[8];
    uint32_t dstB[8];
#pragma unroll
    for (int u = 0; u < 8; u++) {
        int idx = tid + u * 256;              // 0..2047
        int n = idx >> 3, c8 = (idx & 7) * 8;
        dstB[u] = saddr + (uint32_t)(A_BYTES) + (uint32_t)(n * STRH + c8) * 2u;
        srcB[u] = Wt + (size_t)(n0 + n) * K + c8;
    }

#define LOAD_TILE(slot, k0)                                                      \
    do {                                                                         \
        uint32_t so = (uint32_t)(slot) * STAGE_BYTES;                            \
        _Pragma("unroll")                                                        \
        for (int u = 0; u < 4; u++) cp16(dstA[u] + so, srcA[u] + (k0), szA[u]);  \
        _Pragma("unroll")                                                        \
        for (int u = 0; u < 8; u++) cp16(dstB[u] + so, srcB[u] + (k0), 16);      \
    } while (0)

#pragma unroll
    for (int s = 0; s < STAGES - 1; s++) {
        LOAD_TILE(s, s * BK);
        asm volatile("cp.async.commit_group;");
    }

    const int warp = tid >> 5, lane = tid & 31;
    const int mB = (warp >> 2) * 64;          // 2 m-warps
    const int nB = (warp & 3) * 64;           // 4 n-warps
    const int gr = lane >> 2, gc = lane & 3;

    float acc[4][8][4];
#pragma unroll
    for (int i = 0; i < 4; i++)
#pragma unroll
        for (int j = 0; j < 8; j++)
#pragma unroll
            for (int l = 0; l < 4; l++) acc[i][j][l] = 0.f;

    int slot = 0;
    for (int kt = 0; kt < KT; kt++) {
        asm volatile("cp.async.wait_group %0;" :: "n"(STAGES - 2));
        __syncthreads();

        int kload = kt + STAGES - 1;
        if (kload < KT) {
            int ls = kload - STAGES * (kload / STAGES);
            LOAD_TILE(ls, kload * BK);
        }
        asm volatile("cp.async.commit_group;");

        const uint32_t* As = (const uint32_t*)(sm + slot * STAGE_BYTES);
        const uint32_t* Bs = (const uint32_t*)(sm + slot * STAGE_BYTES + A_BYTES);
        slot = (slot == STAGES - 1) ? 0 : slot + 1;

        // 4 k16 steps per tile; smem word stride = 36 per row (banks 4r+gc: conflict-free)
#pragma unroll
        for (int kk = 0; kk < 4; kk++) {
            const int kb = kk * 8 + gc;       // uint32 offset within row
            uint32_t af[4][4], bf[8][2];
#pragma unroll
            for (int mi = 0; mi < 4; mi++) {
                int r = mB + mi * 16 + gr;
                af[mi][0] = As[r * 36 + kb];
                af[mi][1] = As[(r + 8) * 36 + kb];
                af[mi][2] = As[r * 36 + kb + 4];
                af[mi][3] = As[(r + 8) * 36 + kb + 4];
            }
#pragma unroll
            for (int ni = 0; ni < 8; ni++) {
                int cc = nB + ni * 8 + gr;
                bf[ni][0] = Bs[cc * 36 + kb];
                bf[ni][1] = Bs[cc * 36 + kb + 4];
            }
#pragma unroll
            for (int mi = 0; mi < 4; mi++)
#pragma unroll
                for (int ni = 0; ni < 8; ni++)
                    mma_f16(acc[mi][ni], af[mi], bf[ni]);
        }
    }
#undef LOAD_TILE

    // ---- epilogue: +bias, quickGELU, store ----
    const float* bp = bias + (size_t)e * N;
#pragma unroll
    for (int mi = 0; mi < 4; mi++) {
#pragma unroll
        for (int half = 0; half < 2; half++) {
            int lr = mB + mi * 16 + gr + half * 8;
            int grow = m0 + lr;
            if (grow < cnt) {
#pragma unroll
                for (int ni = 0; ni < 8; ni++) {
                    int col = n0 + nB + ni * 8 + gc * 2;
                    float v0 = quick_gelu(acc[mi][ni][half * 2 + 0] + bp[col]);
                    float v1 = quick_gelu(acc[mi][ni][half * 2 + 1] + bp[col + 1]);
                    if (MODE == 1) {
                        __half2 hv = __floats2half2_rn(v0, v1);
                        __half* orow = (__half*)g_h + ((size_t)e * B_TOK + grow) * N;
                        *reinterpret_cast<__half2*>(orow + col) = hv;
                    } else {
                        float* orow = (float*)g_y + ((size_t)e * B_TOK + grow) * N;
                        *reinterpret_cast<float2*>(orow + col) = make_float2(v0, v1);
                    }
                }
            }
        }
    }
}

// ---------------- kernel 4: per-token LayerNorm + weighted combine ----------------
__global__ void combine_kernel(const float* __restrict__ ln_g,
                               const float* __restrict__ ln_b,
                               float* __restrict__ out) {
    const int b = blockIdx.x;
    const int tid = threadIdx.x;
    const int lane = tid & 31, warp = tid >> 5;
    __shared__ float red[16];
    float res[4] = {0.f, 0.f, 0.f, 0.f};

#pragma unroll
    for (int k = 0; k < K_TOP; k++) {
        int e = g_te[b * K_TOP + k];
        int pos = g_tp[b * K_TOP + k];
        float w = g_tw[b * K_TOP + k];
        const float* row = g_y + ((size_t)e * B_TOK + pos) * C_DIM;

        float v[4], s = 0.f, s2 = 0.f;
#pragma unroll
        for (int j = 0; j < 4; j++) {
            v[j] = row[tid + j * 256];
            s += v[j];
            s2 += v[j] * v[j];
        }
#pragma unroll
        for (int o = 16; o > 0; o >>= 1) {
            s  += __shfl_xor_sync(0xffffffffu, s, o);
            s2 += __shfl_xor_sync(0xffffffffu, s2, o);
        }
        if (lane == 0) { red[warp] = s; red[8 + warp] = s2; }
        __syncthreads();
        if (tid == 0) {
            float S = 0.f, S2 = 0.f;
#pragma unroll
            for (int i = 0; i < 8; i++) { S += red[i]; S2 += red[8 + i]; }
            red[0] = S; red[8] = S2;
        }
        __syncthreads();
        float mean = red[0] * (1.f / C_DIM);
        float var  = red[8] * (1.f / C_DIM) - mean * mean;
        float rs = rsqrtf(var + 1e-6f);
        const float* gp  = ln_g + e * C_DIM;
        const float* bp2 = ln_b + e * C_DIM;
#pragma unroll
        for (int j = 0; j < 4; j++) {
            int c = tid + j * 256;
            float nv = (v[j] - mean) * rs;
            res[j] += w * (nv * gp[c] + bp2[c]);
        }
        __syncthreads();
    }
#pragma unroll
    for (int j = 0; j < 4; j++)
        out[(size_t)b * C_DIM + tid + j * 256] = res[j];
}

// ---------------- launch ----------------
extern "C" void kernel_launch(void* const* d_in, const int* in_sizes, int n_in,
                              void* d_out, int out_size) {
    const float* x   = (const float*)d_in[0];
    const float* W1  = (const float*)d_in[1];
    const float* b1  = (const float*)d_in[2];
    const float* W2  = (const float*)d_in[3];
    const float* b2  = (const float*)d_in[4];
    const float* lng = (const float*)d_in[5];
    const float* lnb = (const float*)d_in[6];
    const float* Wg  = (const float*)d_in[7];
    const float* bg  = (const float*)d_in[8];
    float* out = (float*)d_out;

    constexpr int SMEM_BYTES = 3 * (128 * 72 * 2 + 256 * 72 * 2);   // 165888

    cudaFuncSetAttribute(ffn_gemm<C_DIM, H_DIM, 1>,
                         cudaFuncAttributeMaxDynamicSharedMemorySize, SMEM_BYTES);
    cudaFuncSetAttribute(ffn_gemm<H_DIM, C_DIM, 2>,
                         cudaFuncAttributeMaxDynamicSharedMemorySize, SMEM_BYTES);

    __half* w1t; cudaGetSymbolAddress((void**)&w1t, g_w1t);
    __half* w2t; cudaGetSymbolAddress((void**)&w2t, g_w2t);

    zero_counts<<<1, 32>>>();
    convert_x_half<<<1024, 256>>>(x, (B_TOK * C_DIM) / 4);
    transpose_half<C_DIM, H_DIM><<<dim3(C_DIM / 32, H_DIM / 32, E_NUM), dim3(32, 8)>>>(W1, w1t);
    transpose_half<H_DIM, C_DIM><<<dim3(H_DIM / 32, C_DIM / 32, E_NUM), dim3(32, 8)>>>(W2, w2t);
    gate_kernel<<<B_TOK / 8, 256>>>(x, Wg, bg);
    ffn_gemm<C_DIM, H_DIM, 1><<<dim3(H_DIM / 256, B_TOK / 128, E_NUM), 256, SMEM_BYTES>>>(b1);
    ffn_gemm<H_DIM, C_DIM, 2><<<dim3(C_DIM / 256, B_TOK / 128, E_NUM), 256, SMEM_BYTES>>>(b2);
    combine_kernel<<<B_TOK, 256>>>(lng, lnb, out);
}

// round 11
// speedup vs baseline: 4.0125x; 1.1250x over previous
#include <cuda_runtime.h>
#include <cuda_fp16.h>
#include <cstdint>

#define B_TOK 8192
#define C_DIM 1024
#define E_NUM 8
#define K_TOP 4
#define H_DIM 4096

// ---------------- scratch (device globals; no allocations allowed) ----------------
__device__ int    g_count[E_NUM];
__device__ int    g_tok[E_NUM * B_TOK];
__device__ int    g_te[B_TOK * K_TOP];
__device__ int    g_tp[B_TOK * K_TOP];
__device__ float  g_tw[B_TOK * K_TOP];
__device__ __half g_h[(size_t)E_NUM * B_TOK * H_DIM];    // hidden acts, half (512 MiB)
__device__ float  g_y[(size_t)E_NUM * B_TOK * C_DIM];    // expert outputs pre-LN (fp32)
__device__ __half g_xc [(size_t)B_TOK * C_DIM];          // x as half [b][C]
__device__ __half g_w1t[(size_t)E_NUM * H_DIM * C_DIM];  // W1^T: [e][n=H][k=C] half
__device__ __half g_w2t[(size_t)E_NUM * C_DIM * H_DIM];  // W2^T: [e][n=C][k=H] half

// ---------------- helpers ----------------
__device__ __forceinline__ void mma_f16(float (&d)[4], const uint32_t (&a)[4], const uint32_t (&b)[2]) {
    asm volatile(
        "mma.sync.aligned.m16n8k16.row.col.f32.f16.f16.f32 "
        "{%0,%1,%2,%3}, {%4,%5,%6,%7}, {%8,%9}, {%0,%1,%2,%3};\n"
        : "+f"(d[0]), "+f"(d[1]), "+f"(d[2]), "+f"(d[3])
        : "r"(a[0]), "r"(a[1]), "r"(a[2]), "r"(a[3]), "r"(b[0]), "r"(b[1]));
}

__device__ __forceinline__ void cp16(uint32_t dst, const void* src, int sz) {
    asm volatile("cp.async.cg.shared.global [%0], [%1], 16, %2;"
                 :: "r"(dst), "l"(src), "r"(sz));
}

__device__ __forceinline__ float quick_gelu(float v) {
    return v / (1.f + __expf(-1.702f * v));
}

// ---------------- kernel 0: reset counters ----------------
__global__ void zero_counts() {
    if (threadIdx.x < E_NUM) g_count[threadIdx.x] = 0;
}

// ---------------- kernel 0a: x -> half ----------------
__global__ void convert_x_half(const float* __restrict__ src, int n4) {
    uint2* dst = (uint2*)g_xc;
    int i = blockIdx.x * blockDim.x + threadIdx.x;
    int stride = gridDim.x * blockDim.x;
    for (; i < n4; i += stride) {
        float4 v = reinterpret_cast<const float4*>(src)[i];
        __half2 h01 = __floats2half2_rn(v.x, v.y);
        __half2 h23 = __floats2half2_rn(v.z, v.w);
        uint2 o;
        o.x = *reinterpret_cast<uint32_t*>(&h01);
        o.y = *reinterpret_cast<uint32_t*>(&h23);
        dst[i] = o;
    }
}

// ---------------- kernel 0b: transpose + half convert of weights ----------------
// in: [e][KK][NN] fp32 -> out: [e][NN][KK] half
template <int KK, int NN>
__global__ void transpose_half(const float* __restrict__ src, __half* __restrict__ dst) {
    __shared__ float t[32][33];
    const int e = blockIdx.z;
    const float* in = src + (size_t)e * KK * NN;
    __half* out = dst + (size_t)e * NN * KK;
    const int tx = threadIdx.x, ty = threadIdx.y;    // (32, 8)
    const int k0 = blockIdx.x * 32, n0 = blockIdx.y * 32;
#pragma unroll
    for (int i = 0; i < 4; i++) {
        int k = k0 + ty + i * 8;
        t[ty + i * 8][tx] = in[(size_t)k * NN + n0 + tx];
    }
    __syncthreads();
#pragma unroll
    for (int i = 0; i < 4; i++) {
        int n = n0 + ty + i * 8;
        out[(size_t)n * KK + k0 + tx] = __float2half(t[tx][ty + i * 8]);
    }
}

// ---------------- kernel 1: gating (fp32) ----------------
__global__ void gate_kernel(const float* __restrict__ x,
                            const float* __restrict__ Wg,
                            const float* __restrict__ bg) {
    const int warp = threadIdx.x >> 5;
    const int lane = threadIdx.x & 31;
    const int b = blockIdx.x * 8 + warp;

    float acc[E_NUM];
#pragma unroll
    for (int e = 0; e < E_NUM; e++) acc[e] = 0.f;

    const float* xr = x + (size_t)b * C_DIM;
    for (int c = lane; c < C_DIM; c += 32) {
        float xv = xr[c];
        const float* wr = Wg + c * E_NUM;
#pragma unroll
        for (int e = 0; e < E_NUM; e++) acc[e] += xv * wr[e];
    }
#pragma unroll
    for (int e = 0; e < E_NUM; e++)
#pragma unroll
        for (int o = 16; o > 0; o >>= 1)
            acc[e] += __shfl_xor_sync(0xffffffffu, acc[e], o);

    if (lane == 0) {
        float s[E_NUM];
        float mx = -1e30f;
#pragma unroll
        for (int e = 0; e < E_NUM; e++) { s[e] = acc[e] + bg[e]; mx = fmaxf(mx, s[e]); }
        float sum = 0.f;
#pragma unroll
        for (int e = 0; e < E_NUM; e++) { s[e] = __expf(s[e] - mx); sum += s[e]; }
        float inv = 1.f / sum;
#pragma unroll
        for (int e = 0; e < E_NUM; e++) s[e] *= inv;

#pragma unroll
        for (int k = 0; k < K_TOP; k++) {
            int be = 0; float bv = -1.f;
#pragma unroll
            for (int e = 0; e < E_NUM; e++)
                if (s[e] > bv) { bv = s[e]; be = e; }
            s[be] = -2.f;
            int pos = atomicAdd(&g_count[be], 1);
            g_tok[be * B_TOK + pos] = b;
            g_te[b * K_TOP + k] = be;
            g_tp[b * K_TOP + k] = pos;
            g_tw[b * K_TOP + k] = bv;
        }
    }
}

// ---------------- kernels 2 & 3: fp16 cp.async-pipelined grouped GEMM ----------------
// CTA tile 128(M) x 128(N), 256 threads = 8 warps (2m x 4n), warp tile 64x32.
// 2 CTAs/SM (smem 110 KB, ~128 regs/thread) for cross-CTA latency hiding.
// MODE 1: A = gathered g_xc rows, B = g_w1t, out g_h (half).  K=1024 N=4096
// MODE 2: A = g_h rows,           B = g_w2t, out g_y (fp32).  K=4096 N=1024
template <int K, int N, int MODE>
__global__ __launch_bounds__(256, 2)
void ffn_gemm(const float* __restrict__ bias)   // [E, N]
{
    constexpr int BM = 128, BN = 128, BK = 64, STAGES = 3;
    constexpr int STRH = 72;                          // halfs per smem row
    constexpr int A_BYTES = BM * STRH * 2;            // 18432
    constexpr int B_BYTES = BN * STRH * 2;            // 18432
    constexpr int STAGE_BYTES = A_BYTES + B_BYTES;    // 36864
    constexpr int KT = K / BK;

    extern __shared__ char sm[];
    __shared__ int rIdx[BM];

    const int e = blockIdx.z;
    const int cnt = g_count[e];
    const int m0 = blockIdx.y * BM;
    if (m0 >= cnt) return;
    const int n0 = blockIdx.x * BN;
    const int tid = threadIdx.x;

    if (tid < BM) {
        int r = m0 + tid;
        rIdx[tid] = (r < cnt) ? ((MODE == 1) ? g_tok[e * B_TOK + r] : (e * B_TOK + r)) : -1;
    }
    __syncthreads();

    const __half* Abase = (MODE == 1) ? (const __half*)g_xc : (const __half*)g_h;
    const __half* Wt = ((MODE == 1) ? (const __half*)g_w1t : (const __half*)g_w2t)
                       + (size_t)e * (size_t)K * N;   // [N][K]

    // ---- staging plan per stage: A 4 chunks + B 4 chunks of 16B per thread ----
    const uint32_t saddr = (uint32_t)__cvta_generic_to_shared(sm);
    const __half* srcA[4];
    uint32_t dstA[4];
    int szA[4];
#pragma unroll
    for (int u = 0; u < 4; u++) {
        int idx = tid + u * 256;                   // 0..1023
        int row = idx >> 3, c8 = (idx & 7) * 8;    // 8 chunks of 8 halfs per row
        dstA[u] = saddr + (uint32_t)(row * STRH + c8) * 2u;
        int gr = rIdx[row];
        srcA[u] = Abase + (size_t)(gr < 0 ? 0 : gr) * K + c8;
        szA[u] = (gr < 0) ? 0 : 16;
    }
    const __half* srcB[4];
    uint32_t dstB[4];
#pragma unroll
    for (int u = 0; u < 4; u++) {
        int idx = tid + u * 256;                   // 0..1023
        int n = idx >> 3, c8 = (idx & 7) * 8;
        dstB[u] = saddr + (uint32_t)(A_BYTES) + (uint32_t)(n * STRH + c8) * 2u;
        srcB[u] = Wt + (size_t)(n0 + n) * K + c8;
    }

#define LOAD_TILE(slot, k0)                                                      \
    do {                                                                         \
        uint32_t so = (uint32_t)(slot) * STAGE_BYTES;                            \
        _Pragma("unroll")                                                        \
        for (int u = 0; u < 4; u++) cp16(dstA[u] + so, srcA[u] + (k0), szA[u]);  \
        _Pragma("unroll")                                                        \
        for (int u = 0; u < 4; u++) cp16(dstB[u] + so, srcB[u] + (k0), 16);      \
    } while (0)

#pragma unroll
    for (int s = 0; s < STAGES - 1; s++) {
        LOAD_TILE(s, s * BK);
        asm volatile("cp.async.commit_group;");
    }

    const int warp = tid >> 5, lane = tid & 31;
    const int mB = (warp >> 2) * 64;          // 2 m-warps
    const int nB = (warp & 3) * 32;           // 4 n-warps
    const int gr = lane >> 2, gc = lane & 3;

    float acc[4][4][4];
#pragma unroll
    for (int i = 0; i < 4; i++)
#pragma unroll
        for (int j = 0; j < 4; j++)
#pragma unroll
            for (int l = 0; l < 4; l++) acc[i][j][l] = 0.f;

    int slot = 0;
    for (int kt = 0; kt < KT; kt++) {
        asm volatile("cp.async.wait_group %0;" :: "n"(STAGES - 2));
        __syncthreads();

        int kload = kt + STAGES - 1;
        if (kload < KT) {
            int ls = kload - STAGES * (kload / STAGES);
            LOAD_TILE(ls, kload * BK);
        }
        asm volatile("cp.async.commit_group;");

        const uint32_t* As = (const uint32_t*)(sm + slot * STAGE_BYTES);
        const uint32_t* Bs = (const uint32_t*)(sm + slot * STAGE_BYTES + A_BYTES);
        slot = (slot == STAGES - 1) ? 0 : slot + 1;

        // 4 k16 steps per tile; smem word stride 36/row -> (4*gr+gc) conflict-free
#pragma unroll
        for (int kk = 0; kk < 4; kk++) {
            const int kb = kk * 8 + gc;       // uint32 offset within row
            uint32_t af[4][4], bf[4][2];
#pragma unroll
            for (int mi = 0; mi < 4; mi++) {
                int r = mB + mi * 16 + gr;
                af[mi][0] = As[r * 36 + kb];
                af[mi][1] = As[(r + 8) * 36 + kb];
                af[mi][2] = As[r * 36 + kb + 4];
                af[mi][3] = As[(r + 8) * 36 + kb + 4];
            }
#pragma unroll
            for (int ni = 0; ni < 4; ni++) {
                int cc = nB + ni * 8 + gr;
                bf[ni][0] = Bs[cc * 36 + kb];
                bf[ni][1] = Bs[cc * 36 + kb + 4];
            }
#pragma unroll
            for (int mi = 0; mi < 4; mi++)
#pragma unroll
                for (int ni = 0; ni < 4; ni++)
                    mma_f16(acc[mi][ni], af[mi], bf[ni]);
        }
    }
#undef LOAD_TILE

    // ---- epilogue: +bias, quickGELU, store ----
    const float* bp = bias + (size_t)e * N;
#pragma unroll
    for (int mi = 0; mi < 4; mi++) {
#pragma unroll
        for (int half = 0; half < 2; half++) {
            int lr = mB + mi * 16 + gr + half * 8;
            int grow = m0 + lr;
            if (grow < cnt) {
#pragma unroll
                for (int ni = 0; ni < 4; ni++) {
                    int col = n0 + nB + ni * 8 + gc * 2;
                    float v0 = quick_gelu(acc[mi][ni][half * 2 + 0] + bp[col]);
                    float v1 = quick_gelu(acc[mi][ni][half * 2 + 1] + bp[col + 1]);
                    if (MODE == 1) {
                        __half2 hv = __floats2half2_rn(v0, v1);
                        __half* orow = (__half*)g_h + ((size_t)e * B_TOK + grow) * N;
                        *reinterpret_cast<__half2*>(orow + col) = hv;
                    } else {
                        float* orow = (float*)g_y + ((size_t)e * B_TOK + grow) * N;
                        *reinterpret_cast<float2*>(orow + col) = make_float2(v0, v1);
                    }
                }
            }
        }
    }
}

// ---------------- kernel 4: per-token LayerNorm + weighted combine ----------------
__global__ void combine_kernel(const float* __restrict__ ln_g,
                               const float* __restrict__ ln_b,
                               float* __restrict__ out) {
    const int b = blockIdx.x;
    const int tid = threadIdx.x;
    const int lane = tid & 31, warp = tid >> 5;
    __shared__ float red[16];
    float res[4] = {0.f, 0.f, 0.f, 0.f};

#pragma unroll
    for (int k = 0; k < K_TOP; k++) {
        int e = g_te[b * K_TOP + k];
        int pos = g_tp[b * K_TOP + k];
        float w = g_tw[b * K_TOP + k];
        const float* row = g_y + ((size_t)e * B_TOK + pos) * C_DIM;

        float v[4], s = 0.f, s2 = 0.f;
#pragma unroll
        for (int j = 0; j < 4; j++) {
            v[j] = row[tid + j * 256];
            s += v[j];
            s2 += v[j] * v[j];
        }
#pragma unroll
        for (int o = 16; o > 0; o >>= 1) {
            s  += __shfl_xor_sync(0xffffffffu, s, o);
            s2 += __shfl_xor_sync(0xffffffffu, s2, o);
        }
        if (lane == 0) { red[warp] = s; red[8 + warp] = s2; }
        __syncthreads();
        if (tid == 0) {
            float S = 0.f, S2 = 0.f;
#pragma unroll
            for (int i = 0; i < 8; i++) { S += red[i]; S2 += red[8 + i]; }
            red[0] = S; red[8] = S2;
        }
        __syncthreads();
        float mean = red[0] * (1.f / C_DIM);
        float var  = red[8] * (1.f / C_DIM) - mean * mean;
        float rs = rsqrtf(var + 1e-6f);
        const float* gp  = ln_g + e * C_DIM;
        const float* bp2 = ln_b + e * C_DIM;
#pragma unroll
        for (int j = 0; j < 4; j++) {
            int c = tid + j * 256;
            float nv = (v[j] - mean) * rs;
            res[j] += w * (nv * gp[c] + bp2[c]);
        }
        __syncthreads();
    }
#pragma unroll
    for (int j = 0; j < 4; j++)
        out[(size_t)b * C_DIM + tid + j * 256] = res[j];
}

// ---------------- launch ----------------
extern "C" void kernel_launch(void* const* d_in, const int* in_sizes, int n_in,
                              void* d_out, int out_size) {
    const float* x   = (const float*)d_in[0];
    const float* W1  = (const float*)d_in[1];
    const float* b1  = (const float*)d_in[2];
    const float* W2  = (const float*)d_in[3];
    const float* b2  = (const float*)d_in[4];
    const float* lng = (const float*)d_in[5];
    const float* lnb = (const float*)d_in[6];
    const float* Wg  = (const float*)d_in[7];
    const float* bg  = (const float*)d_in[8];
    float* out = (float*)d_out;

    constexpr int SMEM_BYTES = 3 * (128 * 72 * 2 + 128 * 72 * 2);   // 110592

    cudaFuncSetAttribute(ffn_gemm<C_DIM, H_DIM, 1>,
                         cudaFuncAttributeMaxDynamicSharedMemorySize, SMEM_BYTES);
    cudaFuncSetAttribute(ffn_gemm<H_DIM, C_DIM, 2>,
                         cudaFuncAttributeMaxDynamicSharedMemorySize, SMEM_BYTES);

    __half* w1t; cudaGetSymbolAddress((void**)&w1t, g_w1t);
    __half* w2t; cudaGetSymbolAddress((void**)&w2t, g_w2t);

    zero_counts<<<1, 32>>>();
    convert_x_half<<<1024, 256>>>(x, (B_TOK * C_DIM) / 4);
    transpose_half<C_DIM, H_DIM><<<dim3(C_DIM / 32, H_DIM / 32, E_NUM), dim3(32, 8)>>>(W1, w1t);
    transpose_half<H_DIM, C_DIM><<<dim3(H_DIM / 32, C_DIM / 32, E_NUM), dim3(32, 8)>>>(W2, w2t);
    gate_kernel<<<B_TOK / 8, 256>>>(x, Wg, bg);
    ffn_gemm<C_DIM, H_DIM, 1><<<dim3(H_DIM / 128, B_TOK / 128, E_NUM), 256, SMEM_BYTES>>>(b1);
    ffn_gemm<H_DIM, C_DIM, 2><<<dim3(C_DIM / 128, B_TOK / 128, E_NUM), 256, SMEM_BYTES>>>(b2);
    combine_kernel<<<B_TOK, 256>>>(lng, lnb, out);
}

// round 13
// speedup vs baseline: 4.2511x; 1.0594x over previous
#include <cuda_runtime.h>
#include <cuda_fp16.h>
#include <cstdint>

#define B_TOK 8192
#define C_DIM 1024
#define E_NUM 8
#define K_TOP 4
#define H_DIM 4096

// ---------------- scratch (device globals; no allocations allowed) ----------------
__device__ int    g_count[E_NUM];
__device__ int    g_tok[E_NUM * B_TOK];
__device__ int    g_te[B_TOK * K_TOP];
__device__ int    g_tp[B_TOK * K_TOP];
__device__ float  g_tw[B_TOK * K_TOP];
__device__ __half g_h[(size_t)E_NUM * B_TOK * H_DIM];    // hidden acts, half (512 MiB)
__device__ float  g_y[(size_t)E_NUM * B_TOK * C_DIM];    // expert outputs pre-LN (fp32)
__device__ __half g_xc [(size_t)B_TOK * C_DIM];          // x as half [b][C]
__device__ __half g_w1t[(size_t)E_NUM * H_DIM * C_DIM];  // W1^T: [e][n=H][k=C] half
__device__ __half g_w2t[(size_t)E_NUM * C_DIM * H_DIM];  // W2^T: [e][n=C][k=H] half

// ---------------- helpers ----------------
__device__ __forceinline__ void mma_f16(float (&d)[4], const uint32_t (&a)[4], const uint32_t (&b)[2]) {
    asm volatile(
        "mma.sync.aligned.m16n8k16.row.col.f32.f16.f16.f32 "
        "{%0,%1,%2,%3}, {%4,%5,%6,%7}, {%8,%9}, {%0,%1,%2,%3};\n"
        : "+f"(d[0]), "+f"(d[1]), "+f"(d[2]), "+f"(d[3])
        : "r"(a[0]), "r"(a[1]), "r"(a[2]), "r"(a[3]), "r"(b[0]), "r"(b[1]));
}

#define LDSM_X4(r, addr) \
    asm volatile("ldmatrix.sync.aligned.m8n8.x4.shared.b16 {%0,%1,%2,%3}, [%4];" \
                 : "=r"((r)[0]), "=r"((r)[1]), "=r"((r)[2]), "=r"((r)[3]) : "r"(addr))

#define LDSM_X2(r, addr) \
    asm volatile("ldmatrix.sync.aligned.m8n8.x2.shared.b16 {%0,%1}, [%2];" \
                 : "=r"((r)[0]), "=r"((r)[1]) : "r"(addr))

__device__ __forceinline__ void cp16(uint32_t dst, const void* src, int sz) {
    asm volatile("cp.async.cg.shared.global [%0], [%1], 16, %2;"
                 :: "r"(dst), "l"(src), "r"(sz));
}

__device__ __forceinline__ float quick_gelu(float v) {
    return v / (1.f + __expf(-1.702f * v));
}

// ---------------- kernel 0: reset counters ----------------
__global__ void zero_counts() {
    if (threadIdx.x < E_NUM) g_count[threadIdx.x] = 0;
}

// ---------------- kernel 0a: x -> half ----------------
__global__ void convert_x_half(const float* __restrict__ src, int n4) {
    uint2* dst = (uint2*)g_xc;
    int i = blockIdx.x * blockDim.x + threadIdx.x;
    int stride = gridDim.x * blockDim.x;
    for (; i < n4; i += stride) {
        float4 v = reinterpret_cast<const float4*>(src)[i];
        __half2 h01 = __floats2half2_rn(v.x, v.y);
        __half2 h23 = __floats2half2_rn(v.z, v.w);
        uint2 o;
        o.x = *reinterpret_cast<uint32_t*>(&h01);
        o.y = *reinterpret_cast<uint32_t*>(&h23);
        dst[i] = o;
    }
}

// ---------------- kernel 0b: transpose + half convert of weights ----------------
// in: [e][KK][NN] fp32 -> out: [e][NN][KK] half
template <int KK, int NN>
__global__ void transpose_half(const float* __restrict__ src, __half* __restrict__ dst) {
    __shared__ float t[32][33];
    const int e = blockIdx.z;
    const float* in = src + (size_t)e * KK * NN;
    __half* out = dst + (size_t)e * NN * KK;
    const int tx = threadIdx.x, ty = threadIdx.y;    // (32, 8)
    const int k0 = blockIdx.x * 32, n0 = blockIdx.y * 32;
#pragma unroll
    for (int i = 0; i < 4; i++) {
        int k = k0 + ty + i * 8;
        t[ty + i * 8][tx] = in[(size_t)k * NN + n0 + tx];
    }
    __syncthreads();
#pragma unroll
    for (int i = 0; i < 4; i++) {
        int n = n0 + ty + i * 8;
        out[(size_t)n * KK + k0 + tx] = __float2half(t[tx][ty + i * 8]);
    }
}

// ---------------- kernel 1: gating (fp32) ----------------
__global__ void gate_kernel(const float* __restrict__ x,
                            const float* __restrict__ Wg,
                            const float* __restrict__ bg) {
    const int warp = threadIdx.x >> 5;
    const int lane = threadIdx.x & 31;
    const int b = blockIdx.x * 8 + warp;

    float acc[E_NUM];
#pragma unroll
    for (int e = 0; e < E_NUM; e++) acc[e] = 0.f;

    const float* xr = x + (size_t)b * C_DIM;
    for (int c = lane; c < C_DIM; c += 32) {
        float xv = xr[c];
        const float* wr = Wg + c * E_NUM;
#pragma unroll
        for (int e = 0; e < E_NUM; e++) acc[e] += xv * wr[e];
    }
#pragma unroll
    for (int e = 0; e < E_NUM; e++)
#pragma unroll
        for (int o = 16; o > 0; o >>= 1)
            acc[e] += __shfl_xor_sync(0xffffffffu, acc[e], o);

    if (lane == 0) {
        float s[E_NUM];
        float mx = -1e30f;
#pragma unroll
        for (int e = 0; e < E_NUM; e++) { s[e] = acc[e] + bg[e]; mx = fmaxf(mx, s[e]); }
        float sum = 0.f;
#pragma unroll
        for (int e = 0; e < E_NUM; e++) { s[e] = __expf(s[e] - mx); sum += s[e]; }
        float inv = 1.f / sum;
#pragma unroll
        for (int e = 0; e < E_NUM; e++) s[e] *= inv;

#pragma unroll
        for (int k = 0; k < K_TOP; k++) {
            int be = 0; float bv = -1.f;
#pragma unroll
            for (int e = 0; e < E_NUM; e++)
                if (s[e] > bv) { bv = s[e]; be = e; }
            s[be] = -2.f;
            int pos = atomicAdd(&g_count[be], 1);
            g_tok[be * B_TOK + pos] = b;
            g_te[b * K_TOP + k] = be;
            g_tp[b * K_TOP + k] = pos;
            g_tw[b * K_TOP + k] = bv;
        }
    }
}

// ---------------- kernels 2 & 3: fp16 cp.async-pipelined grouped GEMM ----------------
// CTA tile 128(M) x 128(N), 256 threads = 8 warps (2m x 4n), warp tile 64x32.
// 2 CTAs/SM; fragment loads via ldmatrix (LDSM) to cut shared-issue pressure 3x.
// MODE 1: A = gathered g_xc rows, B = g_w1t, out g_h (half).  K=1024 N=4096
// MODE 2: A = g_h rows,           B = g_w2t, out g_y (fp32).  K=4096 N=1024
template <int K, int N, int MODE>
__global__ __launch_bounds__(256, 2)
void ffn_gemm(const float* __restrict__ bias)   // [E, N]
{
    constexpr int BM = 128, BN = 128, BK = 64, STAGES = 3;
    constexpr int STRH = 72;                          // halfs per smem row (144 B)
    constexpr int A_BYTES = BM * STRH * 2;            // 18432
    constexpr int B_BYTES = BN * STRH * 2;            // 18432
    constexpr int STAGE_BYTES = A_BYTES + B_BYTES;    // 36864
    constexpr int KT = K / BK;

    extern __shared__ char sm[];
    __shared__ int rIdx[BM];

    const int e = blockIdx.z;
    const int cnt = g_count[e];
    const int m0 = blockIdx.y * BM;
    if (m0 >= cnt) return;
    const int n0 = blockIdx.x * BN;
    const int tid = threadIdx.x;

    if (tid < BM) {
        int r = m0 + tid;
        rIdx[tid] = (r < cnt) ? ((MODE == 1) ? g_tok[e * B_TOK + r] : (e * B_TOK + r)) : -1;
    }
    __syncthreads();

    const __half* Abase = (MODE == 1) ? (const __half*)g_xc : (const __half*)g_h;
    const __half* Wt = ((MODE == 1) ? (const __half*)g_w1t : (const __half*)g_w2t)
                       + (size_t)e * (size_t)K * N;   // [N][K]

    // ---- staging plan per stage: A 4 chunks + B 4 chunks of 16B per thread ----
    const uint32_t saddr = (uint32_t)__cvta_generic_to_shared(sm);
    const __half* srcA[4];
    uint32_t dstA[4];
    int szA[4];
#pragma unroll
    for (int u = 0; u < 4; u++) {
        int idx = tid + u * 256;                   // 0..1023
        int row = idx >> 3, c8 = (idx & 7) * 8;    // 8 chunks of 8 halfs per row
        dstA[u] = saddr + (uint32_t)(row * STRH + c8) * 2u;
        int gr = rIdx[row];
        srcA[u] = Abase + (size_t)(gr < 0 ? 0 : gr) * K + c8;
        szA[u] = (gr < 0) ? 0 : 16;
    }
    const __half* srcB[4];
    uint32_t dstB[4];
#pragma unroll
    for (int u = 0; u < 4; u++) {
        int idx = tid + u * 256;                   // 0..1023
        int n = idx >> 3, c8 = (idx & 7) * 8;
        dstB[u] = saddr + (uint32_t)(A_BYTES) + (uint32_t)(n * STRH + c8) * 2u;
        srcB[u] = Wt + (size_t)(n0 + n) * K + c8;
    }

#define LOAD_TILE(slot, k0)                                                      \
    do {                                                                         \
        uint32_t so = (uint32_t)(slot) * STAGE_BYTES;                            \
        _Pragma("unroll")                                                        \
        for (int u = 0; u < 4; u++) cp16(dstA[u] + so, srcA[u] + (k0), szA[u]);  \
        _Pragma("unroll")                                                        \
        for (int u = 0; u < 4; u++) cp16(dstB[u] + so, srcB[u] + (k0), 16);      \
    } while (0)

#pragma unroll
    for (int s = 0; s < STAGES - 1; s++) {
        LOAD_TILE(s, s * BK);
        asm volatile("cp.async.commit_group;");
    }

    const int warp = tid >> 5, lane = tid & 31;
    const int mB = (warp >> 2) * 64;          // 2 m-warps
    const int nB = (warp & 3) * 32;           // 4 n-warps
    const int gr = lane >> 2, gc = lane & 3;

    // ldmatrix per-lane address offsets (in halfs, within a stage)
    // A x4: lane l -> row mB + (l&15), k-half (l>>4)*8
    const uint32_t aOff = (uint32_t)((mB + (lane & 15)) * STRH + (lane >> 4) * 8) * 2u;
    // B x2: lane l (0..15 used) -> row nB + (l&7), k-half ((l>>3)&1)*8
    const uint32_t bOff = (uint32_t)(A_BYTES) +
        (uint32_t)((nB + (lane & 7)) * STRH + ((lane >> 3) & 1) * 8) * 2u;

    float acc[4][4][4];
#pragma unroll
    for (int i = 0; i < 4; i++)
#pragma unroll
        for (int j = 0; j < 4; j++)
#pragma unroll
            for (int l = 0; l < 4; l++) acc[i][j][l] = 0.f;

    int slot = 0;
    for (int kt = 0; kt < KT; kt++) {
        asm volatile("cp.async.wait_group %0;" :: "n"(STAGES - 2));
        __syncthreads();

        int kload = kt + STAGES - 1;
        if (kload < KT) {
            int ls = kload - STAGES * (kload / STAGES);
            LOAD_TILE(ls, kload * BK);
        }
        asm volatile("cp.async.commit_group;");

        const uint32_t stageA = saddr + (uint32_t)slot * STAGE_BYTES + aOff;
        const uint32_t stageB = saddr + (uint32_t)slot * STAGE_BYTES + bOff;
        slot = (slot == STAGES - 1) ? 0 : slot + 1;

        // 4 k16 steps per tile; LDSM rows at 144B stride -> conflict-free
#pragma unroll
        for (int kk = 0; kk < 4; kk++) {
            const uint32_t kByte = (uint32_t)kk * 32u;   // 16 halfs per k16 step
            uint32_t af[4][4], bf[4][2];
#pragma unroll
            for (int mi = 0; mi < 4; mi++)
                LDSM_X4(af[mi], stageA + (uint32_t)(mi * 16 * STRH) * 2u + kByte);
#pragma unroll
            for (int ni = 0; ni < 4; ni++)
                LDSM_X2(bf[ni], stageB + (uint32_t)(ni * 8 * STRH) * 2u + kByte);
#pragma unroll
            for (int mi = 0; mi < 4; mi++)
#pragma unroll
                for (int ni = 0; ni < 4; ni++)
                    mma_f16(acc[mi][ni], af[mi], bf[ni]);
        }
    }
#undef LOAD_TILE

    // ---- epilogue: +bias, quickGELU, store ----
    const float* bp = bias + (size_t)e * N;
#pragma unroll
    for (int mi = 0; mi < 4; mi++) {
#pragma unroll
        for (int half = 0; half < 2; half++) {
            int lr = mB + mi * 16 + gr + half * 8;
            int grow = m0 + lr;
            if (grow < cnt) {
#pragma unroll
                for (int ni = 0; ni < 4; ni++) {
                    int col = n0 + nB + ni * 8 + gc * 2;
                    float v0 = quick_gelu(acc[mi][ni][half * 2 + 0] + bp[col]);
                    float v1 = quick_gelu(acc[mi][ni][half * 2 + 1] + bp[col + 1]);
                    if (MODE == 1) {
                        __half2 hv = __floats2half2_rn(v0, v1);
                        __half* orow = (__half*)g_h + ((size_t)e * B_TOK + grow) * N;
                        *reinterpret_cast<__half2*>(orow + col) = hv;
                    } else {
                        float* orow = (float*)g_y + ((size_t)e * B_TOK + grow) * N;
                        *reinterpret_cast<float2*>(orow + col) = make_float2(v0, v1);
                    }
                }
            }
        }
    }
}

// ---------------- kernel 4: per-token LayerNorm + weighted combine ----------------
__global__ void combine_kernel(const float* __restrict__ ln_g,
                               const float* __restrict__ ln_b,
                               float* __restrict__ out) {
    const int b = blockIdx.x;
    const int tid = threadIdx.x;
    const int lane = tid & 31, warp = tid >> 5;
    __shared__ float red[16];
    float res[4] = {0.f, 0.f, 0.f, 0.f};

#pragma unroll
    for (int k = 0; k < K_TOP; k++) {
        int e = g_te[b * K_TOP + k];
        int pos = g_tp[b * K_TOP + k];
        float w = g_tw[b * K_TOP + k];
        const float* row = g_y + ((size_t)e * B_TOK + pos) * C_DIM;

        float v[4], s = 0.f, s2 = 0.f;
#pragma unroll
        for (int j = 0; j < 4; j++) {
            v[j] = row[tid + j * 256];
            s += v[j];
            s2 += v[j] * v[j];
        }
#pragma unroll
        for (int o = 16; o > 0; o >>= 1) {
            s  += __shfl_xor_sync(0xffffffffu, s, o);
            s2 += __shfl_xor_sync(0xffffffffu, s2, o);
        }
        if (lane == 0) { red[warp] = s; red[8 + warp] = s2; }
        __syncthreads();
        if (tid == 0) {
            float S = 0.f, S2 = 0.f;
#pragma unroll
            for (int i = 0; i < 8; i++) { S += red[i]; S2 += red[8 + i]; }
            red[0] = S; red[8] = S2;
        }
        __syncthreads();
        float mean = red[0] * (1.f / C_DIM);
        float var  = red[8] * (1.f / C_DIM) - mean * mean;
        float rs = rsqrtf(var + 1e-6f);
        const float* gp  = ln_g + e * C_DIM;
        const float* bp2 = ln_b + e * C_DIM;
#pragma unroll
        for (int j = 0; j < 4; j++) {
            int c = tid + j * 256;
            float nv = (v[j] - mean) * rs;
            res[j] += w * (nv * gp[c] + bp2[c]);
        }
        __syncthreads();
    }
#pragma unroll
    for (int j = 0; j < 4; j++)
        out[(size_t)b * C_DIM + tid + j * 256] = res[j];
}

// ---------------- launch ----------------
extern "C" void kernel_launch(void* const* d_in, const int* in_sizes, int n_in,
                              void* d_out, int out_size) {
    const float* x   = (const float*)d_in[0];
    const float* W1  = (const float*)d_in[1];
    const float* b1  = (const float*)d_in[2];
    const float* W2  = (const float*)d_in[3];
    const float* b2  = (const float*)d_in[4];
    const float* lng = (const float*)d_in[5];
    const float* lnb = (const float*)d_in[6];
    const float* Wg  = (const float*)d_in[7];
    const float* bg  = (const float*)d_in[8];
    float* out = (float*)d_out;

    constexpr int SMEM_BYTES = 3 * (128 * 72 * 2 + 128 * 72 * 2);   // 110592

    cudaFuncSetAttribute(ffn_gemm<C_DIM, H_DIM, 1>,
                         cudaFuncAttributeMaxDynamicSharedMemorySize, SMEM_BYTES);
    cudaFuncSetAttribute(ffn_gemm<H_DIM, C_DIM, 2>,
                         cudaFuncAttributeMaxDynamicSharedMemorySize, SMEM_BYTES);

    __half* w1t; cudaGetSymbolAddress((void**)&w1t, g_w1t);
    __half* w2t; cudaGetSymbolAddress((void**)&w2t, g_w2t);

    zero_counts<<<1, 32>>>();
    convert_x_half<<<1024, 256>>>(x, (B_TOK * C_DIM) / 4);
    transpose_half<C_DIM, H_DIM><<<dim3(C_DIM / 32, H_DIM / 32, E_NUM), dim3(32, 8)>>>(W1, w1t);
    transpose_half<H_DIM, C_DIM><<<dim3(H_DIM / 32, C_DIM / 32, E_NUM), dim3(32, 8)>>>(W2, w2t);
    gate_kernel<<<B_TOK / 8, 256>>>(x, Wg, bg);
    ffn_gemm<C_DIM, H_DIM, 1><<<dim3(H_DIM / 128, B_TOK / 128, E_NUM), 256, SMEM_BYTES>>>(b1);
    ffn_gemm<H_DIM, C_DIM, 2><<<dim3(C_DIM / 128, B_TOK / 128, E_NUM), 256, SMEM_BYTES>>>(b2);
    combine_kernel<<<B_TOK, 256>>>(lng, lnb, out);
}

// round 15
// speedup vs baseline: 4.3669x; 1.0272x over previous
#include <cuda_runtime.h>
#include <cuda_fp16.h>
#include <cstdint>

#define B_TOK 8192
#define C_DIM 1024
#define E_NUM 8
#define K_TOP 4
#define H_DIM 4096

// ---------------- scratch (device globals; no allocations allowed) ----------------
__device__ int    g_count[E_NUM];
__device__ int    g_tok[E_NUM * B_TOK];
__device__ int    g_te[B_TOK * K_TOP];
__device__ int    g_tp[B_TOK * K_TOP];
__device__ float  g_tw[B_TOK * K_TOP];
__device__ __half g_h[(size_t)E_NUM * B_TOK * H_DIM];    // hidden acts, half (512 MiB)
__device__ float  g_y[(size_t)E_NUM * B_TOK * C_DIM];    // expert outputs pre-LN (fp32)
__device__ __half g_xc [(size_t)B_TOK * C_DIM];          // x as half [b][C]
__device__ __half g_w1h[(size_t)E_NUM * C_DIM * H_DIM];  // W1 as half [e][K=C][N=H]
__device__ __half g_w2h[(size_t)E_NUM * H_DIM * C_DIM];  // W2 as half [e][K=H][N=C]

// ---------------- helpers ----------------
__device__ __forceinline__ void mma_f16(float (&d)[4], const uint32_t (&a)[4], const uint32_t (&b)[2]) {
    asm volatile(
        "mma.sync.aligned.m16n8k16.row.col.f32.f16.f16.f32 "
        "{%0,%1,%2,%3}, {%4,%5,%6,%7}, {%8,%9}, {%0,%1,%2,%3};\n"
        : "+f"(d[0]), "+f"(d[1]), "+f"(d[2]), "+f"(d[3])
        : "r"(a[0]), "r"(a[1]), "r"(a[2]), "r"(a[3]), "r"(b[0]), "r"(b[1]));
}

#define LDSM_X4(r, addr) \
    asm volatile("ldmatrix.sync.aligned.m8n8.x4.shared.b16 {%0,%1,%2,%3}, [%4];" \
                 : "=r"((r)[0]), "=r"((r)[1]), "=r"((r)[2]), "=r"((r)[3]) : "r"(addr))

#define LDSM_X4_T(r, addr) \
    asm volatile("ldmatrix.sync.aligned.m8n8.x4.trans.shared.b16 {%0,%1,%2,%3}, [%4];" \
                 : "=r"((r)[0]), "=r"((r)[1]), "=r"((r)[2]), "=r"((r)[3]) : "r"(addr))

__device__ __forceinline__ void cp16(uint32_t dst, const void* src, int sz) {
    asm volatile("cp.async.cg.shared.global [%0], [%1], 16, %2;"
                 :: "r"(dst), "l"(src), "r"(sz));
}

__device__ __forceinline__ float quick_gelu(float v) {
    return v / (1.f + __expf(-1.702f * v));
}

// ---------------- kernel 0: reset counters ----------------
__global__ void zero_counts() {
    if (threadIdx.x < E_NUM) g_count[threadIdx.x] = 0;
}

// ---------------- kernel 0a: weights fp32 -> half (same layout) ----------------
__global__ void convert_w_half(const float* __restrict__ src, __half* __restrict__ dst, int n4) {
    int i = blockIdx.x * blockDim.x + threadIdx.x;
    int stride = gridDim.x * blockDim.x;
    uint2* d2 = (uint2*)dst;
    for (; i < n4; i += stride) {
        float4 v = reinterpret_cast<const float4*>(src)[i];
        __half2 h01 = __floats2half2_rn(v.x, v.y);
        __half2 h23 = __floats2half2_rn(v.z, v.w);
        uint2 o;
        o.x = *reinterpret_cast<uint32_t*>(&h01);
        o.y = *reinterpret_cast<uint32_t*>(&h23);
        d2[i] = o;
    }
}

// ---------------- kernel 1: gating (fp32, numerics unchanged) + x->half ----------------
__global__ void gate_kernel(const float* __restrict__ x,
                            const float* __restrict__ Wg,
                            const float* __restrict__ bg) {
    const int warp = threadIdx.x >> 5;
    const int lane = threadIdx.x & 31;
    const int b = blockIdx.x * 8 + warp;

    float acc[E_NUM];
#pragma unroll
    for (int e = 0; e < E_NUM; e++) acc[e] = 0.f;

    const float* xr = x + (size_t)b * C_DIM;
    __half* xh = (__half*)g_xc + (size_t)b * C_DIM;
    for (int c = lane; c < C_DIM; c += 32) {
        float xv = xr[c];
        xh[c] = __float2half(xv);                  // fused conversion (write-only side effect)
        const float* wr = Wg + c * E_NUM;
#pragma unroll
        for (int e = 0; e < E_NUM; e++) acc[e] += xv * wr[e];
    }
#pragma unroll
    for (int e = 0; e < E_NUM; e++)
#pragma unroll
        for (int o = 16; o > 0; o >>= 1)
            acc[e] += __shfl_xor_sync(0xffffffffu, acc[e], o);

    if (lane == 0) {
        float s[E_NUM];
        float mx = -1e30f;
#pragma unroll
        for (int e = 0; e < E_NUM; e++) { s[e] = acc[e] + bg[e]; mx = fmaxf(mx, s[e]); }
        float sum = 0.f;
#pragma unroll
        for (int e = 0; e < E_NUM; e++) { s[e] = __expf(s[e] - mx); sum += s[e]; }
        float inv = 1.f / sum;
#pragma unroll
        for (int e = 0; e < E_NUM; e++) s[e] *= inv;

#pragma unroll
        for (int k = 0; k < K_TOP; k++) {
            int be = 0; float bv = -1.f;
#pragma unroll
            for (int e = 0; e < E_NUM; e++)
                if (s[e] > bv) { bv = s[e]; be = e; }
            s[be] = -2.f;
            int pos = atomicAdd(&g_count[be], 1);
            g_tok[be * B_TOK + pos] = b;
            g_te[b * K_TOP + k] = be;
            g_tp[b * K_TOP + k] = pos;
            g_tw[b * K_TOP + k] = bv;
        }
    }
}

// ---------------- kernels 2 & 3: fp16 cp.async-pipelined grouped GEMM ----------------
// CTA tile 128(M) x 128(N), 256 threads = 8 warps (2m x 4n), warp tile 64x32. 2 CTAs/SM.
// A smem [m][k] (72-half rows), fragments via LDSM.x4.
// B smem [k][n] (136-half rows) staged straight from W [K][N]; fragments via LDSM.x4.trans.
// MODE 1: A = gathered g_xc rows, B = g_w1h, out g_h (half).  K=1024 N=4096
// MODE 2: A = g_h rows,           B = g_w2h, out g_y (fp32).  K=4096 N=1024
template <int K, int N, int MODE>
__global__ __launch_bounds__(256, 2)
void ffn_gemm(const float* __restrict__ bias)   // [E, N]
{
    constexpr int BM = 128, BN = 128, BK = 64, STAGES = 3;
    constexpr int ASTR = 72;                          // halfs per A smem row (144 B)
    constexpr int BSTR = 136;                         // halfs per B smem row (272 B)
    constexpr int A_BYTES = BM * ASTR * 2;            // 18432
    constexpr int B_BYTES = BK * BSTR * 2;            // 17408
    constexpr int STAGE_BYTES = A_BYTES + B_BYTES;    // 35840
    constexpr int KT = K / BK;

    extern __shared__ char sm[];
    __shared__ int rIdx[BM];

    const int e = blockIdx.z;
    const int cnt = g_count[e];
    const int m0 = blockIdx.y * BM;
    if (m0 >= cnt) return;
    const int n0 = blockIdx.x * BN;
    const int tid = threadIdx.x;

    if (tid < BM) {
        int r = m0 + tid;
        rIdx[tid] = (r < cnt) ? ((MODE == 1) ? g_tok[e * B_TOK + r] : (e * B_TOK + r)) : -1;
    }
    __syncthreads();

    const __half* Abase = (MODE == 1) ? (const __half*)g_xc : (const __half*)g_h;
    const __half* Wh = ((MODE == 1) ? (const __half*)g_w1h : (const __half*)g_w2h)
                       + (size_t)e * (size_t)K * N;   // [K][N]

    // ---- staging plan per stage: A 4 + B 4 chunks of 16B per thread ----
    const uint32_t saddr = (uint32_t)__cvta_generic_to_shared(sm);
    const __half* srcA[4];
    uint32_t dstA[4];
    int szA[4];
#pragma unroll
    for (int u = 0; u < 4; u++) {
        int idx = tid + u * 256;                   // 0..1023
        int row = idx >> 3, c8 = (idx & 7) * 8;    // 8 chunks of 8 halfs per row
        dstA[u] = saddr + (uint32_t)(row * ASTR + c8) * 2u;
        int gr = rIdx[row];
        srcA[u] = Abase + (size_t)(gr < 0 ? 0 : gr) * K + c8;
        szA[u] = (gr < 0) ? 0 : 16;
    }
    const __half* srcB[4];                         // B tile: 64 k-rows x 128 halfs
    uint32_t dstB[4];
#pragma unroll
    for (int u = 0; u < 4; u++) {
        int idx = tid + u * 256;                   // 0..1023
        int r = idx >> 4, c16 = idx & 15;          // 16 chunks of 8 halfs per k-row
        dstB[u] = saddr + (uint32_t)A_BYTES + (uint32_t)(r * BSTR + c16 * 8) * 2u;
        srcB[u] = Wh + (size_t)r * N + n0 + c16 * 8;
    }

#define LOAD_TILE(slot, k0)                                                          \
    do {                                                                             \
        uint32_t so = (uint32_t)(slot) * STAGE_BYTES;                                \
        _Pragma("unroll")                                                            \
        for (int u = 0; u < 4; u++) cp16(dstA[u] + so, srcA[u] + (k0), szA[u]);      \
        _Pragma("unroll")                                                            \
        for (int u = 0; u < 4; u++)                                                  \
            cp16(dstB[u] + so, srcB[u] + (size_t)(k0) * N, 16);                      \
    } while (0)

#pragma unroll
    for (int s = 0; s < STAGES - 1; s++) {
        LOAD_TILE(s, s * BK);
        asm volatile("cp.async.commit_group;");
    }

    const int warp = tid >> 5, lane = tid & 31;
    const int mB = (warp >> 2) * 64;          // 2 m-warps
    const int nB = (warp & 3) * 32;           // 4 n-warps
    const int gr = lane >> 2, gc = lane & 3;

    // A ldmatrix x4: lane l -> row mB + (l&15), k-half (l>>4)*8
    const uint32_t aOff = (uint32_t)((mB + (lane & 15)) * ASTR + (lane >> 4) * 8) * 2u;
    // B ldmatrix x4 trans: group j = lane>>3: k_local = (j&1)*8 + (lane&7), n_local = (j>>1)*8
    const int bj = lane >> 3, brin = lane & 7;
    const uint32_t bOff = (uint32_t)A_BYTES +
        (uint32_t)((((bj & 1) << 3) + brin) * BSTR + nB + ((bj >> 1) << 3)) * 2u;

    float acc[4][4][4];
#pragma unroll
    for (int i = 0; i < 4; i++)
#pragma unroll
        for (int j = 0; j < 4; j++)
#pragma unroll
            for (int l = 0; l < 4; l++) acc[i][j][l] = 0.f;

    int slot = 0;
    for (int kt = 0; kt < KT; kt++) {
        asm volatile("cp.async.wait_group %0;" :: "n"(STAGES - 2));
        __syncthreads();

        int kload = kt + STAGES - 1;
        if (kload < KT) {
            int ls = kload - STAGES * (kload / STAGES);
            LOAD_TILE(ls, kload * BK);
        }
        asm volatile("cp.async.commit_group;");

        const uint32_t stageA = saddr + (uint32_t)slot * STAGE_BYTES + aOff;
        const uint32_t stageB = saddr + (uint32_t)slot * STAGE_BYTES + bOff;
        slot = (slot == STAGES - 1) ? 0 : slot + 1;

#pragma unroll
        for (int kk = 0; kk < 4; kk++) {
            uint32_t af[4][4], bf[4][2];
#pragma unroll
            for (int mi = 0; mi < 4; mi++)
                LDSM_X4(af[mi], stageA + (uint32_t)(mi * 16 * ASTR) * 2u + (uint32_t)kk * 32u);
            // two x4.trans loads cover the warp's 32 n-columns (16 each)
#pragma unroll
            for (int np = 0; np < 2; np++) {
                uint32_t t[4];
                LDSM_X4_T(t, stageB + (uint32_t)(kk * 16 * BSTR) * 2u + (uint32_t)np * 32u);
                bf[2 * np + 0][0] = t[0];
                bf[2 * np + 0][1] = t[1];
                bf[2 * np + 1][0] = t[2];
                bf[2 * np + 1][1] = t[3];
            }
#pragma unroll
            for (int mi = 0; mi < 4; mi++)
#pragma unroll
                for (int ni = 0; ni < 4; ni++)
                    mma_f16(acc[mi][ni], af[mi], bf[ni]);
        }
    }
#undef LOAD_TILE

    // ---- epilogue: +bias, quickGELU, store ----
    const float* bp = bias + (size_t)e * N;
#pragma unroll
    for (int mi = 0; mi < 4; mi++) {
#pragma unroll
        for (int half = 0; half < 2; half++) {
            int lr = mB + mi * 16 + gr + half * 8;
            int grow = m0 + lr;
            if (grow < cnt) {
#pragma unroll
                for (int ni = 0; ni < 4; ni++) {
                    int col = n0 + nB + ni * 8 + gc * 2;
                    float v0 = quick_gelu(acc[mi][ni][half * 2 + 0] + bp[col]);
                    float v1 = quick_gelu(acc[mi][ni][half * 2 + 1] + bp[col + 1]);
                    if (MODE == 1) {
                        __half2 hv = __floats2half2_rn(v0, v1);
                        __half* orow = (__half*)g_h + ((size_t)e * B_TOK + grow) * N;
                        *reinterpret_cast<__half2*>(orow + col) = hv;
                    } else {
                        float* orow = (float*)g_y + ((size_t)e * B_TOK + grow) * N;
                        *reinterpret_cast<float2*>(orow + col) = make_float2(v0, v1);
                    }
                }
            }
        }
    }
}

// ---------------- kernel 4: per-token LayerNorm + weighted combine ----------------
__global__ void combine_kernel(const float* __restrict__ ln_g,
                               const float* __restrict__ ln_b,
                               float* __restrict__ out) {
    const int b = blockIdx.x;
    const int tid = threadIdx.x;
    const int lane = tid & 31, warp = tid >> 5;
    __shared__ float red[16];
    float res[4] = {0.f, 0.f, 0.f, 0.f};

#pragma unroll
    for (int k = 0; k < K_TOP; k++) {
        int e = g_te[b * K_TOP + k];
        int pos = g_tp[b * K_TOP + k];
        float w = g_tw[b * K_TOP + k];
        const float* row = g_y + ((size_t)e * B_TOK + pos) * C_DIM;

        float v[4], s = 0.f, s2 = 0.f;
#pragma unroll
        for (int j = 0; j < 4; j++) {
            v[j] = row[tid + j * 256];
            s += v[j];
            s2 += v[j] * v[j];
        }
#pragma unroll
        for (int o = 16; o > 0; o >>= 1) {
            s  += __shfl_xor_sync(0xffffffffu, s, o);
            s2 += __shfl_xor_sync(0xffffffffu, s2, o);
        }
        if (lane == 0) { red[warp] = s; red[8 + warp] = s2; }
        __syncthreads();
        if (tid == 0) {
            float S = 0.f, S2 = 0.f;
#pragma unroll
            for (int i = 0; i < 8; i++) { S += red[i]; S2 += red[8 + i]; }
            red[0] = S; red[8] = S2;
        }
        __syncthreads();
        float mean = red[0] * (1.f / C_DIM);
        float var  = red[8] * (1.f / C_DIM) - mean * mean;
        float rs = rsqrtf(var + 1e-6f);
        const float* gp  = ln_g + e * C_DIM;
        const float* bp2 = ln_b + e * C_DIM;
#pragma unroll
        for (int j = 0; j < 4; j++) {
            int c = tid + j * 256;
            float nv = (v[j] - mean) * rs;
            res[j] += w * (nv * gp[c] + bp2[c]);
        }
        __syncthreads();
    }
#pragma unroll
    for (int j = 0; j < 4; j++)
        out[(size_t)b * C_DIM + tid + j * 256] = res[j];
}

// ---------------- launch ----------------
extern "C" void kernel_launch(void* const* d_in, const int* in_sizes, int n_in,
                              void* d_out, int out_size) {
    const float* x   = (const float*)d_in[0];
    const float* W1  = (const float*)d_in[1];
    const float* b1  = (const float*)d_in[2];
    const float* W2  = (const float*)d_in[3];
    const float* b2  = (const float*)d_in[4];
    const float* lng = (const float*)d_in[5];
    const float* lnb = (const float*)d_in[6];
    const float* Wg  = (const float*)d_in[7];
    const float* bg  = (const float*)d_in[8];
    float* out = (float*)d_out;

    constexpr int SMEM_BYTES = 3 * (128 * 72 * 2 + 64 * 136 * 2);   // 107520

    cudaFuncSetAttribute(ffn_gemm<C_DIM, H_DIM, 1>,
                         cudaFuncAttributeMaxDynamicSharedMemorySize, SMEM_BYTES);
    cudaFuncSetAttribute(ffn_gemm<H_DIM, C_DIM, 2>,
                         cudaFuncAttributeMaxDynamicSharedMemorySize, SMEM_BYTES);

    __half* w1h; cudaGetSymbolAddress((void**)&w1h, g_w1h);
    __half* w2h; cudaGetSymbolAddress((void**)&w2h, g_w2h);

    zero_counts<<<1, 32>>>();
    gate_kernel<<<B_TOK / 8, 256>>>(x, Wg, bg);                     // also emits g_xc (half)
    convert_w_half<<<2048, 256>>>(W1, w1h, (E_NUM * C_DIM * H_DIM) / 4);
    convert_w_half<<<2048, 256>>>(W2, w2h, (E_NUM * H_DIM * C_DIM) / 4);
    ffn_gemm<C_DIM, H_DIM, 1><<<dim3(H_DIM / 128, B_TOK / 128, E_NUM), 256, SMEM_BYTES>>>(b1);
    ffn_gemm<H_DIM, C_DIM, 2><<<dim3(C_DIM / 128, B_TOK / 128, E_NUM), 256, SMEM_BYTES>>>(b2);
    combine_kernel<<<B_TOK, 256>>>(lng, lnb, out);
}

// round 16
// speedup vs baseline: 4.4027x; 1.0082x over previous
#include <cuda_runtime.h>
#include <cuda_fp16.h>
#include <cstdint>

#define B_TOK 8192
#define C_DIM 1024
#define E_NUM 8
#define K_TOP 4
#define H_DIM 4096

// ---------------- scratch (device globals; no allocations allowed) ----------------
__device__ int    g_count[E_NUM];
__device__ int    g_tok[E_NUM * B_TOK];
__device__ int    g_te[B_TOK * K_TOP];
__device__ int    g_tp[B_TOK * K_TOP];
__device__ float  g_tw[B_TOK * K_TOP];
__device__ __half g_h[(size_t)E_NUM * B_TOK * H_DIM];    // hidden acts, half (512 MiB)
__device__ float  g_y[(size_t)E_NUM * B_TOK * C_DIM];    // expert outputs pre-LN (fp32)
__device__ __half g_xc [(size_t)B_TOK * C_DIM];          // x as half [b][C]
__device__ __half g_w1h[(size_t)E_NUM * C_DIM * H_DIM];  // W1 as half [e][K=C][N=H]
__device__ __half g_w2h[(size_t)E_NUM * H_DIM * C_DIM];  // W2 as half [e][K=H][N=C]

// ---------------- helpers ----------------
__device__ __forceinline__ void mma_f16(float (&d)[4], const uint32_t (&a)[4], const uint32_t (&b)[2]) {
    asm volatile(
        "mma.sync.aligned.m16n8k16.row.col.f32.f16.f16.f32 "
        "{%0,%1,%2,%3}, {%4,%5,%6,%7}, {%8,%9}, {%0,%1,%2,%3};\n"
        : "+f"(d[0]), "+f"(d[1]), "+f"(d[2]), "+f"(d[3])
        : "r"(a[0]), "r"(a[1]), "r"(a[2]), "r"(a[3]), "r"(b[0]), "r"(b[1]));
}

#define LDSM_X4(r, addr) \
    asm volatile("ldmatrix.sync.aligned.m8n8.x4.shared.b16 {%0,%1,%2,%3}, [%4];" \
                 : "=r"((r)[0]), "=r"((r)[1]), "=r"((r)[2]), "=r"((r)[3]) : "r"(addr))

#define LDSM_X4_T(r, addr) \
    asm volatile("ldmatrix.sync.aligned.m8n8.x4.trans.shared.b16 {%0,%1,%2,%3}, [%4];" \
                 : "=r"((r)[0]), "=r"((r)[1]), "=r"((r)[2]), "=r"((r)[3]) : "r"(addr))

__device__ __forceinline__ void cp16(uint32_t dst, const void* src, int sz) {
    asm volatile("cp.async.cg.shared.global [%0], [%1], 16, %2;"
                 :: "r"(dst), "l"(src), "r"(sz));
}

__device__ __forceinline__ float quick_gelu(float v) {
    return v / (1.f + __expf(-1.702f * v));
}

// ---------------- kernel 0: both weight converts + counter zeroing, one launch ----------------
__global__ void convert_weights(const float* __restrict__ W1, const float* __restrict__ W2) {
    if (blockIdx.x == 0 && threadIdx.x < E_NUM) g_count[threadIdx.x] = 0;
    constexpr int n4 = (E_NUM * C_DIM * H_DIM) / 4;   // float4 count per weight tensor
    uint2* d1 = (uint2*)g_w1h;
    uint2* d2 = (uint2*)g_w2h;
    int i = blockIdx.x * blockDim.x + threadIdx.x;
    const int stride = gridDim.x * blockDim.x;
    for (; i < 2 * n4; i += stride) {
        const float4* s;
        uint2* d;
        int idx;
        if (i < n4) { s = (const float4*)W1; d = d1; idx = i; }
        else        { s = (const float4*)W2; d = d2; idx = i - n4; }
        float4 v = s[idx];
        __half2 h01 = __floats2half2_rn(v.x, v.y);
        __half2 h23 = __floats2half2_rn(v.z, v.w);
        uint2 o;
        o.x = *reinterpret_cast<uint32_t*>(&h01);
        o.y = *reinterpret_cast<uint32_t*>(&h23);
        d[idx] = o;
    }
}

// ---------------- kernel 1: gating (fp32, numerics unchanged) + x->half ----------------
__global__ void gate_kernel(const float* __restrict__ x,
                            const float* __restrict__ Wg,
                            const float* __restrict__ bg) {
    const int warp = threadIdx.x >> 5;
    const int lane = threadIdx.x & 31;
    const int b = blockIdx.x * 8 + warp;

    float acc[E_NUM];
#pragma unroll
    for (int e = 0; e < E_NUM; e++) acc[e] = 0.f;

    const float* xr = x + (size_t)b * C_DIM;
    __half* xh = (__half*)g_xc + (size_t)b * C_DIM;
    for (int c = lane; c < C_DIM; c += 32) {
        float xv = xr[c];
        xh[c] = __float2half(xv);                  // fused conversion (write-only side effect)
        const float* wr = Wg + c * E_NUM;
#pragma unroll
        for (int e = 0; e < E_NUM; e++) acc[e] += xv * wr[e];
    }
#pragma unroll
    for (int e = 0; e < E_NUM; e++)
#pragma unroll
        for (int o = 16; o > 0; o >>= 1)
            acc[e] += __shfl_xor_sync(0xffffffffu, acc[e], o);

    if (lane == 0) {
        float s[E_NUM];
        float mx = -1e30f;
#pragma unroll
        for (int e = 0; e < E_NUM; e++) { s[e] = acc[e] + bg[e]; mx = fmaxf(mx, s[e]); }
        float sum = 0.f;
#pragma unroll
        for (int e = 0; e < E_NUM; e++) { s[e] = __expf(s[e] - mx); sum += s[e]; }
        float inv = 1.f / sum;
#pragma unroll
        for (int e = 0; e < E_NUM; e++) s[e] *= inv;

#pragma unroll
        for (int k = 0; k < K_TOP; k++) {
            int be = 0; float bv = -1.f;
#pragma unroll
            for (int e = 0; e < E_NUM; e++)
                if (s[e] > bv) { bv = s[e]; be = e; }
            s[be] = -2.f;
            int pos = atomicAdd(&g_count[be], 1);
            g_tok[be * B_TOK + pos] = b;
            g_te[b * K_TOP + k] = be;
            g_tp[b * K_TOP + k] = pos;
            g_tw[b * K_TOP + k] = bv;
        }
    }
}

// ---------------- kernels 2 & 3: fp16 cp.async-pipelined grouped GEMM ----------------
// CTA tile 128(M) x 128(N), 256 threads = 8 warps (2m x 4n), warp tile 64x32. 2 CTAs/SM.
// A smem [m][k] (72-half rows), fragments via LDSM.x4.
// B smem [k][n] (136-half rows) staged straight from W [K][N]; fragments via LDSM.x4.trans.
// MODE 1: A = gathered g_xc rows, B = g_w1h, out g_h (half).  K=1024 N=4096
// MODE 2: A = g_h rows,           B = g_w2h, out g_y (fp32).  K=4096 N=1024
template <int K, int N, int MODE>
__global__ __launch_bounds__(256, 2)
void ffn_gemm(const float* __restrict__ bias)   // [E, N]
{
    constexpr int BM = 128, BN = 128, BK = 64, STAGES = 3;
    constexpr int ASTR = 72;                          // halfs per A smem row (144 B)
    constexpr int BSTR = 136;                         // halfs per B smem row (272 B)
    constexpr int A_BYTES = BM * ASTR * 2;            // 18432
    constexpr int B_BYTES = BK * BSTR * 2;            // 17408
    constexpr int STAGE_BYTES = A_BYTES + B_BYTES;    // 35840
    constexpr int KT = K / BK;

    extern __shared__ char sm[];
    __shared__ int rIdx[BM];

    const int e = blockIdx.z;
    const int cnt = g_count[e];
    const int m0 = blockIdx.y * BM;
    if (m0 >= cnt) return;
    const int n0 = blockIdx.x * BN;
    const int tid = threadIdx.x;

    if (tid < BM) {
        int r = m0 + tid;
        rIdx[tid] = (r < cnt) ? ((MODE == 1) ? g_tok[e * B_TOK + r] : (e * B_TOK + r)) : -1;
    }
    __syncthreads();

    const __half* Abase = (MODE == 1) ? (const __half*)g_xc : (const __half*)g_h;
    const __half* Wh = ((MODE == 1) ? (const __half*)g_w1h : (const __half*)g_w2h)
                       + (size_t)e * (size_t)K * N;   // [K][N]

    // ---- staging plan per stage: A 4 + B 4 chunks of 16B per thread ----
    const uint32_t saddr = (uint32_t)__cvta_generic_to_shared(sm);
    const __half* srcA[4];
    uint32_t dstA[4];
    int szA[4];
#pragma unroll
    for (int u = 0; u < 4; u++) {
        int idx = tid + u * 256;                   // 0..1023
        int row = idx >> 3, c8 = (idx & 7) * 8;    // 8 chunks of 8 halfs per row
        dstA[u] = saddr + (uint32_t)(row * ASTR + c8) * 2u;
        int gr = rIdx[row];
        srcA[u] = Abase + (size_t)(gr < 0 ? 0 : gr) * K + c8;
        szA[u] = (gr < 0) ? 0 : 16;
    }
    const __half* srcB[4];                         // B tile: 64 k-rows x 128 halfs
    uint32_t dstB[4];
#pragma unroll
    for (int u = 0; u < 4; u++) {
        int idx = tid + u * 256;                   // 0..1023
        int r = idx >> 4, c16 = idx & 15;          // 16 chunks of 8 halfs per k-row
        dstB[u] = saddr + (uint32_t)A_BYTES + (uint32_t)(r * BSTR + c16 * 8) * 2u;
        srcB[u] = Wh + (size_t)r * N + n0 + c16 * 8;
    }

#define LOAD_TILE(slot, k0)                                                          \
    do {                                                                             \
        uint32_t so = (uint32_t)(slot) * STAGE_BYTES;                                \
        _Pragma("unroll")                                                            \
        for (int u = 0; u < 4; u++) cp16(dstA[u] + so, srcA[u] + (k0), szA[u]);      \
        _Pragma("unroll")                                                            \
        for (int u = 0; u < 4; u++)                                                  \
            cp16(dstB[u] + so, srcB[u] + (size_t)(k0) * N, 16);                      \
    } while (0)

#pragma unroll
    for (int s = 0; s < STAGES - 1; s++) {
        LOAD_TILE(s, s * BK);
        asm volatile("cp.async.commit_group;");
    }

    const int warp = tid >> 5, lane = tid & 31;
    const int mB = (warp >> 2) * 64;          // 2 m-warps
    const int nB = (warp & 3) * 32;           // 4 n-warps
    const int gr = lane >> 2, gc = lane & 3;

    // A ldmatrix x4: lane l -> row mB + (l&15), k-half (l>>4)*8
    const uint32_t aOff = (uint32_t)((mB + (lane & 15)) * ASTR + (lane >> 4) * 8) * 2u;
    // B ldmatrix x4 trans: group j = lane>>3: k_local = (j&1)*8 + (lane&7), n_local = (j>>1)*8
    const int bj = lane >> 3, brin = lane & 7;
    const uint32_t bOff = (uint32_t)A_BYTES +
        (uint32_t)((((bj & 1) << 3) + brin) * BSTR + nB + ((bj >> 1) << 3)) * 2u;

    float acc[4][4][4];
#pragma unroll
    for (int i = 0; i < 4; i++)
#pragma unroll
        for (int j = 0; j < 4; j++)
#pragma unroll
            for (int l = 0; l < 4; l++) acc[i][j][l] = 0.f;

    int slot = 0;
    for (int kt = 0; kt < KT; kt++) {
        asm volatile("cp.async.wait_group %0;" :: "n"(STAGES - 2));
        __syncthreads();

        int kload = kt + STAGES - 1;
        if (kload < KT) {
            int ls = kload - STAGES * (kload / STAGES);
            LOAD_TILE(ls, kload * BK);
        }
        asm volatile("cp.async.commit_group;");

        const uint32_t stageA = saddr + (uint32_t)slot * STAGE_BYTES + aOff;
        const uint32_t stageB = saddr + (uint32_t)slot * STAGE_BYTES + bOff;
        slot = (slot == STAGES - 1) ? 0 : slot + 1;

#pragma unroll
        for (int kk = 0; kk < 4; kk++) {
            uint32_t af[4][4], bf[4][2];
#pragma unroll
            for (int mi = 0; mi < 4; mi++)
                LDSM_X4(af[mi], stageA + (uint32_t)(mi * 16 * ASTR) * 2u + (uint32_t)kk * 32u);
            // two x4.trans loads cover the warp's 32 n-columns (16 each)
#pragma unroll
            for (int np = 0; np < 2; np++) {
                uint32_t t[4];
                LDSM_X4_T(t, stageB + (uint32_t)(kk * 16 * BSTR) * 2u + (uint32_t)np * 32u);
                bf[2 * np + 0][0] = t[0];
                bf[2 * np + 0][1] = t[1];
                bf[2 * np + 1][0] = t[2];
                bf[2 * np + 1][1] = t[3];
            }
#pragma unroll
            for (int mi = 0; mi < 4; mi++)
#pragma unroll
                for (int ni = 0; ni < 4; ni++)
                    mma_f16(acc[mi][ni], af[mi], bf[ni]);
        }
    }
#undef LOAD_TILE

    // ---- epilogue: +bias, quickGELU, store ----
    const float* bp = bias + (size_t)e * N;
#pragma unroll
    for (int mi = 0; mi < 4; mi++) {
#pragma unroll
        for (int half = 0; half < 2; half++) {
            int lr = mB + mi * 16 + gr + half * 8;
            int grow = m0 + lr;
            if (grow < cnt) {
#pragma unroll
                for (int ni = 0; ni < 4; ni++) {
                    int col = n0 + nB + ni * 8 + gc * 2;
                    float v0 = quick_gelu(acc[mi][ni][half * 2 + 0] + bp[col]);
                    float v1 = quick_gelu(acc[mi][ni][half * 2 + 1] + bp[col + 1]);
                    if (MODE == 1) {
                        __half2 hv = __floats2half2_rn(v0, v1);
                        __half* orow = (__half*)g_h + ((size_t)e * B_TOK + grow) * N;
                        *reinterpret_cast<__half2*>(orow + col) = hv;
                    } else {
                        float* orow = (float*)g_y + ((size_t)e * B_TOK + grow) * N;
                        *reinterpret_cast<float2*>(orow + col) = make_float2(v0, v1);
                    }
                }
            }
        }
    }
}

// ---------------- kernel 4: parallel per-token LayerNorm + weighted combine ----------------
// 8 warps: 2 warps per expert-k; all 4 rows stream concurrently; 2 block barriers total.
__global__ void combine_kernel(const float* __restrict__ ln_g,
                               const float* __restrict__ ln_b,
                               float* __restrict__ out) {
    const int b = blockIdx.x;
    const int tid = threadIdx.x;
    const int lane = tid & 31, warp = tid >> 5;
    const int kk = warp >> 1, hf = warp & 1;      // expert slot, row half

    __shared__ float con[K_TOP][C_DIM];           // per-k contributions (16 KB)
    __shared__ float red[K_TOP][2][2];            // [k][half][{sum, sumsq}]

    const int e   = g_te[b * K_TOP + kk];
    const int pos = g_tp[b * K_TOP + kk];
    const float w = g_tw[b * K_TOP + kk];
    const float* row = g_y + ((size_t)e * B_TOK + pos) * C_DIM;
    const int base = hf * 512;

    float v[16], s = 0.f, s2 = 0.f;
#pragma unroll
    for (int j = 0; j < 16; j++) {
        v[j] = row[base + lane + j * 32];
        s += v[j];
        s2 += v[j] * v[j];
    }
#pragma unroll
    for (int o = 16; o > 0; o >>= 1) {
        s  += __shfl_xor_sync(0xffffffffu, s, o);
        s2 += __shfl_xor_sync(0xffffffffu, s2, o);
    }
    if (lane == 0) { red[kk][hf][0] = s; red[kk][hf][1] = s2; }
    __syncthreads();

    const float S  = red[kk][0][0] + red[kk][1][0];
    const float S2 = red[kk][0][1] + red[kk][1][1];
    const float mean = S * (1.f / C_DIM);
    const float var  = S2 * (1.f / C_DIM) - mean * mean;
    const float rs = rsqrtf(var + 1e-6f);
    const float* gp  = ln_g + e * C_DIM;
    const float* bp2 = ln_b + e * C_DIM;
#pragma unroll
    for (int j = 0; j < 16; j++) {
        int c = base + lane + j * 32;
        con[kk][c] = w * ((v[j] - mean) * rs * gp[c] + bp2[c]);
    }
    __syncthreads();

#pragma unroll
    for (int j = 0; j < 4; j++) {
        int c = tid + j * 256;
        out[(size_t)b * C_DIM + c] = con[0][c] + con[1][c] + con[2][c] + con[3][c];
    }
}

// ---------------- launch ----------------
extern "C" void kernel_launch(void* const* d_in, const int* in_sizes, int n_in,
                              void* d_out, int out_size) {
    const float* x   = (const float*)d_in[0];
    const float* W1  = (const float*)d_in[1];
    const float* b1  = (const float*)d_in[2];
    const float* W2  = (const float*)d_in[3];
    const float* b2  = (const float*)d_in[4];
    const float* lng = (const float*)d_in[5];
    const float* lnb = (const float*)d_in[6];
    const float* Wg  = (const float*)d_in[7];
    const float* bg  = (const float*)d_in[8];
    float* out = (float*)d_out;

    constexpr int SMEM_BYTES = 3 * (128 * 72 * 2 + 64 * 136 * 2);   // 107520

    cudaFuncSetAttribute(ffn_gemm<C_DIM, H_DIM, 1>,
                         cudaFuncAttributeMaxDynamicSharedMemorySize, SMEM_BYTES);
    cudaFuncSetAttribute(ffn_gemm<H_DIM, C_DIM, 2>,
                         cudaFuncAttributeMaxDynamicSharedMemorySize, SMEM_BYTES);

    convert_weights<<<4096, 256>>>(W1, W2);      // also zeroes g_count (block 0)
    gate_kernel<<<B_TOK / 8, 256>>>(x, Wg, bg);  // also emits g_xc (half)
    ffn_gemm<C_DIM, H_DIM, 1><<<dim3(H_DIM / 128, B_TOK / 128, E_NUM), 256, SMEM_BYTES>>>(b1);
    ffn_gemm<H_DIM, C_DIM, 2><<<dim3(C_DIM / 128, B_TOK / 128, E_NUM), 256, SMEM_BYTES>>>(b2);
    combine_kernel<<<B_TOK, 256>>>(lng, lnb, out);
}